// round 14
// baseline (speedup 1.0000x reference)
#include <cuda_runtime.h>
#include <cuda_fp16.h>
#include <math.h>
#include <stdint.h>

// Problem constants
#define B_     2
#define S_     2048
#define HID_   2048
#define NH_    16
#define DQ_    192
#define DNOPE_ 128
#define DROPE_ 64
#define DV_    128
#define RANK_  512
#define M_     (B_*S_)            // 4096
#define NQ_    (NH_*DQ_)          // 3072
#define NKV_   (NH_*(DNOPE_+DV_)) // 4096
#define CKVW_  (RANK_+DROPE_)     // 576

// Scratch (device globals; no runtime allocation allowed)
__device__ __half g_HIDh[M_*HID_];    // fp16 hidden
__device__ __half g_QWh [NQ_*HID_];   // fp16 weights
__device__ __half g_KAWh[CKVW_*HID_];
__device__ __half g_KBWh[NKV_*RANK_];
__device__ __half g_OWh [HID_*HID_];
__device__ __half g_Qh  [M_*NQ_];     // fp16 q projection (rope in place)
__device__ float  g_CKV [M_*CKVW_];   // kv_a output fp32 (c | k_pe raw)
__device__ __half g_CLNh[M_*RANK_];   // rmsnormed c (fp16)
__device__ __half g_KVh [M_*NKV_];    // fp16 kv_b output (k_nope | v)
__device__ __half g_KPEh[M_*DROPE_];  // fp16 rotated k_pe
__device__ __half g_AOh [M_*NH_*DV_]; // fp16 attention output

// ---------------------------------------------------------------------------
// Helpers
// ---------------------------------------------------------------------------
__device__ __forceinline__ uint32_t smem_u32(const void* p) {
    uint32_t a;
    asm("{ .reg .u64 t; cvta.to.shared.u64 t, %1; cvt.u32.u64 %0, t; }" : "=r"(a) : "l"(p));
    return a;
}
__device__ __forceinline__ unsigned h2u(float a, float b) {
    __half2 h = __floats2half2_rn(a, b);
    return *(unsigned*)&h;
}
// fp16 mma m16n8k16, fp32 accumulate
#define MMA16(C, A, B0, B1) \
    asm volatile("mma.sync.aligned.m16n8k16.row.col.f32.f16.f16.f32 " \
        "{%0,%1,%2,%3},{%4,%5,%6,%7},{%8,%9},{%0,%1,%2,%3};" \
        : "+f"((C)[0]), "+f"((C)[1]), "+f"((C)[2]), "+f"((C)[3]) \
        : "r"((A)[0]), "r"((A)[1]), "r"((A)[2]), "r"((A)[3]), "r"(B0), "r"(B1))

#define LDSM4(R, addr) \
    asm volatile("ldmatrix.sync.aligned.m8n8.x4.shared.b16 {%0,%1,%2,%3}, [%4];" \
        : "=r"((R)[0]), "=r"((R)[1]), "=r"((R)[2]), "=r"((R)[3]) : "r"(addr))
#define LDSM4T(R, addr) \
    asm volatile("ldmatrix.sync.aligned.m8n8.x4.trans.shared.b16 {%0,%1,%2,%3}, [%4];" \
        : "=r"((R)[0]), "=r"((R)[1]), "=r"((R)[2]), "=r"((R)[3]) : "r"(addr))

#define CPA16(dst, src) \
    asm volatile("cp.async.cg.shared.global [%0], [%1], 16;" :: "r"(dst), "l"(src))
#define CPA_COMMIT() asm volatile("cp.async.commit_group;" ::: "memory")
#define CPA_WAIT0()  asm volatile("cp.async.wait_group 0;" ::: "memory")

// Swizzled smem offset: rs-byte rows (rs multiple of 128), 16B chunk c
__device__ __forceinline__ uint32_t offN(uint32_t row, uint32_t rs, uint32_t c) {
    return row * rs + ((c >> 3) << 7) + (((c ^ row) & 7u) << 4);
}

// output store: fp32 or fp16 pair
__device__ __forceinline__ void store2(float* p, float a, float b) {
    *(float2*)p = make_float2(a, b);
}
__device__ __forceinline__ void store2(__half* p, float a, float b) {
    *(__half2*)p = __floats2half2_rn(a, b);
}

// ---------------------------------------------------------------------------
// fp32 -> fp16 bulk convert (8 elts/thread)
// ---------------------------------------------------------------------------
__global__ void cvt_h(const float* __restrict__ s, __half* __restrict__ d) {
    int i = (blockIdx.x * 256 + threadIdx.x) * 8;
    float4 a = *(const float4*)(s + i);
    float4 b = *(const float4*)(s + i + 4);
    uint4 pk;
    pk.x = h2u(a.x, a.y); pk.y = h2u(a.z, a.w);
    pk.z = h2u(b.x, b.y); pk.w = h2u(b.z, b.w);
    *(uint4*)(d + i) = pk;
}

// ---------------------------------------------------------------------------
// fp16 NT GEMM via cp.async: C[M][N] = A[M][K] * W[N][K]^T (A,W fp16)
// Tile 128x128x64, 256 threads, warps 4x2, double-buffered, 1 barrier/slab.
// DYNAMIC smem: 2 stages x (A 16K | B 16K) = 64K.  (unchanged from R10)
// ---------------------------------------------------------------------------
#define GEMM_SMEM (2 * 32768)

template <typename OutT>
__global__ __launch_bounds__(256, 2)
void gemm_h16(const __half* __restrict__ A, const __half* __restrict__ W,
              OutT* __restrict__ C, int M, int N, int K) {
    extern __shared__ __align__(16) uint8_t smraw[];
    uint32_t sb = smem_u32(smraw);
    int tid = threadIdx.x, lane = tid & 31, warp = tid >> 5;
    int wm = warp >> 1, wn = warp & 1;
    int m0 = blockIdx.y * 128, n0 = blockIdx.x * 128;

    int rJ[4], cJ[4], rnJ[4];
    #pragma unroll
    for (int i = 0; i < 4; i++) {
        int idx = tid + i * 256;
        rJ[i] = idx >> 3; cJ[i] = idx & 7;
        int rn = n0 + rJ[i]; rnJ[i] = (rn > N - 1) ? (N - 1) : rn;
    }

    auto stage = [&](int s, int st) {
        uint32_t ab = sb + st * 32768, bb = ab + 16384;
        int kof = s * 64;
        #pragma unroll
        for (int i = 0; i < 4; i++) {
            CPA16(ab + offN(rJ[i], 128, cJ[i]),
                  A + (size_t)(m0 + rJ[i]) * K + kof + cJ[i] * 8);
            CPA16(bb + offN(rJ[i], 128, cJ[i]),
                  W + (size_t)rnJ[i] * K + kof + cJ[i] * 8);
        }
        CPA_COMMIT();
    };

    float acc[2][8][4];
    #pragma unroll
    for (int a = 0; a < 2; a++)
        #pragma unroll
        for (int b = 0; b < 8; b++)
            #pragma unroll
            for (int c = 0; c < 4; c++) acc[a][b][c] = 0.0f;

    stage(0, 0);
    int ns = K >> 6;
    for (int s = 0; s < ns; s++) {
        int st = s & 1;
        CPA_WAIT0();           // slab s arrived
        __syncthreads();       // visible to all; prev compute done (buf reuse)
        if (s + 1 < ns) stage(s + 1, st ^ 1);   // prefetch (async)
        uint32_t ab = sb + st * 32768, bb = ab + 16384;
        #pragma unroll
        for (int ks = 0; ks < 4; ks++) {
            unsigned af[2][4];
            #pragma unroll
            for (int mt = 0; mt < 2; mt++) {
                uint32_t row = wm * 32 + mt * 16 + (lane & 15);
                uint32_t c = ks * 2 + (lane >> 4);
                LDSM4(af[mt], ab + offN(row, 128, c));
            }
            #pragma unroll
            for (int nb = 0; nb < 4; nb++) {
                unsigned bf[4];
                uint32_t rowb = wn * 64 + nb * 16 + (lane & 7) + ((lane >> 4) << 3);
                uint32_t cb = ks * 2 + ((lane >> 3) & 1);
                LDSM4(bf, bb + offN(rowb, 128, cb));
                MMA16(acc[0][nb*2],   af[0], bf[0], bf[1]);
                MMA16(acc[0][nb*2+1], af[0], bf[2], bf[3]);
                MMA16(acc[1][nb*2],   af[1], bf[0], bf[1]);
                MMA16(acc[1][nb*2+1], af[1], bf[2], bf[3]);
            }
        }
    }

    #pragma unroll
    for (int mt = 0; mt < 2; mt++) {
        int r0 = m0 + wm * 32 + mt * 16 + (lane >> 2);
        #pragma unroll
        for (int nt = 0; nt < 8; nt++) {
            int cb = n0 + wn * 64 + nt * 8 + (lane & 3) * 2;
            if (cb < N) {
                store2(&C[(size_t)r0 * N + cb],       acc[mt][nt][0], acc[mt][nt][1]);
                store2(&C[(size_t)(r0 + 8) * N + cb], acc[mt][nt][2], acc[mt][nt][3]);
            }
        }
    }
}

// ---------------------------------------------------------------------------
// RMSNorm over first 512 of each 576-wide CKV row, times gamma -> fp16.
// ---------------------------------------------------------------------------
__global__ void rmsnorm_k(const float* __restrict__ ckv, const float* __restrict__ w,
                          __half* __restrict__ out) {
    int m = blockIdx.x;
    int tid = threadIdx.x;   // 128 threads
    const float* row = ckv + (size_t)m * CKVW_;
    float4 v = *(const float4*)(row + tid * 4);
    float ss = v.x*v.x + v.y*v.y + v.z*v.z + v.w*v.w;
    #pragma unroll
    for (int o = 16; o; o >>= 1) ss += __shfl_xor_sync(0xffffffffu, ss, o);
    __shared__ float sacc[4];
    if ((tid & 31) == 0) sacc[tid >> 5] = ss;
    __syncthreads();
    float tot = sacc[0] + sacc[1] + sacc[2] + sacc[3];
    float inv = rsqrtf(tot * (1.0f/512.0f) + 1e-6f);
    float4 wv = *(const float4*)(w + tid * 4);
    uint2 pk;
    pk.x = h2u(v.x*inv*wv.x, v.y*inv*wv.y);
    pk.y = h2u(v.z*inv*wv.z, v.w*inv*wv.w);
    *(uint2*)(out + (size_t)m * RANK_ + tid * 4) = pk;
}

// ---------------------------------------------------------------------------
// YaRN rope (low=10, high=23, mscale ratio = 1). Position = m % S_.
// ---------------------------------------------------------------------------
__device__ __forceinline__ float yarn_inv_freq(int j) {
    float fe = powf(10000.0f, -(float)(2*j) / 64.0f);
    float fi = fe * (1.0f / 40.0f);
    float ramp = fminf(fmaxf(((float)j - 10.0f) * (1.0f/13.0f), 0.0f), 1.0f);
    return fi * ramp + fe * (1.0f - ramp);
}

__global__ void rope_q(__half* __restrict__ Q) {
    int warp = (blockIdx.x * blockDim.x + threadIdx.x) >> 5;
    int lane = threadIdx.x & 31;
    int m = warp >> 4, h = warp & 15;
    __half* p = Q + (size_t)m * NQ_ + h * DQ_ + DNOPE_;
    float x0 = __half2float(p[2*lane]), x1 = __half2float(p[2*lane+1]);
    float ang = (float)(m % S_) * yarn_inv_freq(lane);
    float s, c;
    sincosf(ang, &s, &c);
    float y0 = x0*c - x1*s;
    float y1 = x1*c + x0*s;
    __syncwarp();
    p[lane]      = __float2half(y0);
    p[lane + 32] = __float2half(y1);
}

__global__ void rope_k(const float* __restrict__ ckv, __half* __restrict__ kpe) {
    int warp = (blockIdx.x * blockDim.x + threadIdx.x) >> 5;
    int lane = threadIdx.x & 31;
    const float* p = ckv + (size_t)warp * CKVW_ + RANK_;
    float x0 = p[2*lane], x1 = p[2*lane+1];
    float ang = (float)(warp % S_) * yarn_inv_freq(lane);
    float s, c;
    sincosf(ang, &s, &c);
    kpe[(size_t)warp * DROPE_ + lane]      = __float2half(x0*c - x1*s);
    kpe[(size_t)warp * DROPE_ + lane + 32] = __float2half(x1*c + x0*s);
}

// ---------------------------------------------------------------------------
// Flash attention FA2-style, fp16 mma, cp.async double-buffered K/V.
// Block = (bofs batch, h, 64-q tile), 128 threads / 4 warps. Each warp owns a
// 16-row q stripe x full 64-key tile: warp-local softmax, in-register P, ONE
// __syncthreads per k-tile. Q loaded to REGISTERS once at kt==0 (smem Qs is
// read exactly once); (128,2) -> 255-reg budget, ~180 used, no spills.
// Smem: Qs [64][192]h @0 (24K) | buf st @ 24576+st*40960: K 24K | V 16K.
// Total 106496 B -> 2 CTAs/SM.
// ---------------------------------------------------------------------------
#define AQ_OFF 0
#define BUF_OFF(st) (24576 + (st)*40960)
#define ATTN_SMEM 106496

__global__ __launch_bounds__(128, 2)
void attn_fa2(const __half* __restrict__ Qh, const __half* __restrict__ KVh,
              const __half* __restrict__ KPEh, __half* __restrict__ AOh, int bofs) {
    extern __shared__ __align__(16) uint8_t smraw[];
    uint32_t sb = smem_u32(smraw);

    int tid = threadIdx.x, lane = tid & 31, warp = tid >> 5;
    int qt = gridDim.x - 1 - blockIdx.x;   // reverse: heavy tiles first
    int h = blockIdx.y, b = bofs;
    int q0 = qt * 64;
    const size_t base = (size_t)b * S_;

    auto stage_tile = [&](int kt, int st) {
        int k0 = kt * 64;
        uint32_t kb = sb + BUF_OFF(st), vb = kb + 24576;
        #pragma unroll
        for (int i = 0; i < 12; i++) {   // K: 64 rows x 24 chunks
            int idx = tid + i * 128;
            int r = idx / 24, c = idx % 24;
            const __half* src = (c < 16)
                ? KVh  + (base + k0 + r) * NKV_ + h * 256 + c * 8
                : KPEh + (base + k0 + r) * (size_t)DROPE_ + (c - 16) * 8;
            CPA16(kb + offN(r, 384, c), src);
        }
        #pragma unroll
        for (int i = 0; i < 8; i++) {    // V: 64 rows x 16 chunks
            int idx = tid + i * 128;
            int r = idx / 16, c = idx % 16;
            const __half* src = KVh + (base + k0 + r) * NKV_ + h * 256 + 128 + c * 8;
            CPA16(vb + offN(r, 256, c), src);
        }
        CPA_COMMIT();
    };

    // stage Q (once) + tile 0 as one group
    #pragma unroll
    for (int i = 0; i < 12; i++) {
        int idx = tid + i * 128;
        int r = idx / 24, c = idx % 24;
        const __half* src = Qh + (base + q0 + r) * NQ_ + h * DQ_ + c * 8;
        CPA16(sb + AQ_OFF + offN(r, 384, c), src);
    }
    stage_tile(0, 0);

    int wq = warp * 16;
    int grow0 = q0 + wq + (lane >> 2);   // global q rows of this thread
    int grow1 = grow0 + 8;

    float m_r[2] = {-INFINITY, -INFINITY};
    float l_r[2] = {0.0f, 0.0f};
    float o[16][4];
    #pragma unroll
    for (int nt = 0; nt < 16; nt++)
        #pragma unroll
        for (int j = 0; j < 4; j++) o[nt][j] = 0.0f;

    unsigned qf[12][4];                  // Q fragments (registers, loaded kt==0)

    const float scale = 0.072168783648703f;   // 1/sqrt(192)

    for (int kt = 0; kt <= qt; kt++) {
        int k0 = kt * 64;
        int st = kt & 1;
        uint32_t kbuf = sb + BUF_OFF(st), vbuf = kbuf + 24576;
        CPA_WAIT0();           // tile kt (and Q) arrived
        __syncthreads();       // visibility + prior compute done (buf reuse)
        if (kt < qt) stage_tile(kt + 1, st ^ 1);   // async prefetch
        if (kt == 0) {
            #pragma unroll
            for (int ks = 0; ks < 12; ks++) {
                uint32_t row = wq + (lane & 15);
                uint32_t c = ks * 2 + (lane >> 4);
                LDSM4(qf[ks], sb + AQ_OFF + offN(row, 384, c));
            }
        }

        // S = Q K^T : warp m16 x n64, 12 k16 steps (Q from registers)
        float sacc[8][4];
        #pragma unroll
        for (int nt = 0; nt < 8; nt++)
            #pragma unroll
            for (int j = 0; j < 4; j++) sacc[nt][j] = 0.0f;
        #pragma unroll
        for (int ks = 0; ks < 12; ks++) {
            #pragma unroll
            for (int nb = 0; nb < 4; nb++) {
                unsigned kb[4];
                uint32_t rowb = nb * 16 + (lane & 7) + ((lane >> 4) << 3);
                uint32_t cb = ks * 2 + ((lane >> 3) & 1);
                LDSM4(kb, kbuf + offN(rowb, 384, cb));
                MMA16(sacc[nb*2],   qf[ks], kb[0], kb[1]);
                MMA16(sacc[nb*2+1], qf[ks], kb[2], kb[3]);
            }
        }
        // scale + causal mask (only tiles straddling the diagonal)
        bool diag = (k0 + 63 > q0 + wq);
        #pragma unroll
        for (int nt = 0; nt < 8; nt++) {
            int cb = k0 + nt * 8 + (lane & 3) * 2;
            #pragma unroll
            for (int j = 0; j < 4; j++) {
                float v = sacc[nt][j] * scale;
                if (diag) {
                    int col = cb + (j & 1);
                    int row = (j < 2) ? grow0 : grow1;
                    if (col > row) v = -1e30f;
                }
                sacc[nt][j] = v;
            }
        }
        // warp-local online softmax
        float mx0 = -INFINITY, mx1 = -INFINITY;
        #pragma unroll
        for (int nt = 0; nt < 8; nt++) {
            mx0 = fmaxf(mx0, fmaxf(sacc[nt][0], sacc[nt][1]));
            mx1 = fmaxf(mx1, fmaxf(sacc[nt][2], sacc[nt][3]));
        }
        mx0 = fmaxf(mx0, __shfl_xor_sync(0xffffffffu, mx0, 1));
        mx0 = fmaxf(mx0, __shfl_xor_sync(0xffffffffu, mx0, 2));
        mx1 = fmaxf(mx1, __shfl_xor_sync(0xffffffffu, mx1, 1));
        mx1 = fmaxf(mx1, __shfl_xor_sync(0xffffffffu, mx1, 2));
        float nm0 = fmaxf(m_r[0], mx0), nm1 = fmaxf(m_r[1], mx1);
        float corr0 = __expf(m_r[0] - nm0), corr1 = __expf(m_r[1] - nm1);
        m_r[0] = nm0; m_r[1] = nm1;

        float rs0 = 0.0f, rs1 = 0.0f;
        #pragma unroll
        for (int nt = 0; nt < 8; nt++) {
            sacc[nt][0] = __expf(sacc[nt][0] - nm0);
            sacc[nt][1] = __expf(sacc[nt][1] - nm0);
            sacc[nt][2] = __expf(sacc[nt][2] - nm1);
            sacc[nt][3] = __expf(sacc[nt][3] - nm1);
            rs0 += sacc[nt][0] + sacc[nt][1];
            rs1 += sacc[nt][2] + sacc[nt][3];
        }
        rs0 += __shfl_xor_sync(0xffffffffu, rs0, 1);
        rs0 += __shfl_xor_sync(0xffffffffu, rs0, 2);
        rs1 += __shfl_xor_sync(0xffffffffu, rs1, 1);
        rs1 += __shfl_xor_sync(0xffffffffu, rs1, 2);
        l_r[0] = l_r[0] * corr0 + rs0;
        l_r[1] = l_r[1] * corr1 + rs1;

        // O = O*corr + P V. P: in-register C-frag -> A-frag conversion.
        #pragma unroll
        for (int nt = 0; nt < 16; nt++) {
            o[nt][0] *= corr0; o[nt][1] *= corr0;
            o[nt][2] *= corr1; o[nt][3] *= corr1;
        }
        #pragma unroll
        for (int ks = 0; ks < 4; ks++) {
            unsigned pa[4];
            pa[0] = h2u(sacc[ks*2][0],   sacc[ks*2][1]);
            pa[1] = h2u(sacc[ks*2][2],   sacc[ks*2][3]);
            pa[2] = h2u(sacc[ks*2+1][0], sacc[ks*2+1][1]);
            pa[3] = h2u(sacc[ks*2+1][2], sacc[ks*2+1][3]);
            #pragma unroll
            for (int nb = 0; nb < 8; nb++) {
                unsigned vb[4];
                uint32_t row = ks * 16 + (lane & 7) + (((lane >> 3) & 1) << 3);
                uint32_t c = nb * 2 + (lane >> 4);
                LDSM4T(vb, vbuf + offN(row, 256, c));
                MMA16(o[nb*2],   pa, vb[0], vb[1]);
                MMA16(o[nb*2+1], pa, vb[2], vb[3]);
            }
        }
    }

    // epilogue: normalize, write fp16 AO[b,q,h*128+d]
    float inv0 = 1.0f / l_r[0], inv1 = 1.0f / l_r[1];
    #pragma unroll
    for (int nt = 0; nt < 16; nt++) {
        int d = nt * 8 + (lane & 3) * 2;
        size_t r0 = (base + grow0) * (size_t)(NH_*DV_) + h*DV_ + d;
        size_t r1 = (base + grow1) * (size_t)(NH_*DV_) + h*DV_ + d;
        store2(&AOh[r0], o[nt][0]*inv0, o[nt][1]*inv0);
        store2(&AOh[r1], o[nt][2]*inv1, o[nt][3]*inv1);
    }
}

// ---------------------------------------------------------------------------
// Launch: fork-join streams. Front-end: Q branch || KV branch (as R13).
// Back-end: attention split per batch; O-proj(b0) on s1 overlaps attn(b1).
// ---------------------------------------------------------------------------
extern "C" void kernel_launch(void* const* d_in, const int* in_sizes, int n_in,
                              void* d_out, int out_size) {
    const float* hidden = (const float*)d_in[0];
    const float* q_w    = (const float*)d_in[2];
    const float* kv_a_w = (const float*)d_in[3];
    const float* ln_w   = (const float*)d_in[4];
    const float* kv_b_w = (const float*)d_in[5];
    const float* o_w    = (const float*)d_in[6];
    float*       out    = (float*)d_out;

    __half *hHID, *hQW, *hKAW, *hKBW, *hOW, *pQh, *pKVh, *pKPEh, *pCLNh, *pAOh;
    float  *pCKV;
    cudaGetSymbolAddress((void**)&hHID,  g_HIDh);
    cudaGetSymbolAddress((void**)&hQW,   g_QWh);
    cudaGetSymbolAddress((void**)&hKAW,  g_KAWh);
    cudaGetSymbolAddress((void**)&hKBW,  g_KBWh);
    cudaGetSymbolAddress((void**)&hOW,   g_OWh);
    cudaGetSymbolAddress((void**)&pQh,   g_Qh);
    cudaGetSymbolAddress((void**)&pCKV,  g_CKV);
    cudaGetSymbolAddress((void**)&pCLNh, g_CLNh);
    cudaGetSymbolAddress((void**)&pKVh,  g_KVh);
    cudaGetSymbolAddress((void**)&pKPEh, g_KPEh);
    cudaGetSymbolAddress((void**)&pAOh,  g_AOh);

    cudaFuncSetAttribute(attn_fa2, cudaFuncAttributeMaxDynamicSharedMemorySize,
                         (int)ATTN_SMEM);
    cudaFuncSetAttribute(gemm_h16<__half>, cudaFuncAttributeMaxDynamicSharedMemorySize,
                         (int)GEMM_SMEM);
    cudaFuncSetAttribute(gemm_h16<float>, cudaFuncAttributeMaxDynamicSharedMemorySize,
                         (int)GEMM_SMEM);

    cudaStream_t s1;
    cudaStreamCreateWithFlags(&s1, cudaStreamNonBlocking);
    cudaEvent_t eFork, eJoin, eA0, eO0;
    cudaEventCreateWithFlags(&eFork, cudaEventDisableTiming);
    cudaEventCreateWithFlags(&eJoin, cudaEventDisableTiming);
    cudaEventCreateWithFlags(&eA0,   cudaEventDisableTiming);
    cudaEventCreateWithFlags(&eO0,   cudaEventDisableTiming);

    dim3 blk(256);
    // ---- main stream: hidden cvt (shared dependency) ----
    cvt_h<<<(M_*HID_)/2048, 256>>>(hidden, hHID);
    cudaEventRecord(eFork, 0);

    // ---- branch s1: Q projection chain (+ o_w cvt) ----
    cudaStreamWaitEvent(s1, eFork, 0);
    cvt_h<<<(NQ_*HID_)/2048, 256, 0, s1>>>(q_w, hQW);
    gemm_h16<__half><<<dim3(NQ_/128, M_/128), blk, GEMM_SMEM, s1>>>(hHID, hQW, pQh, M_, NQ_, HID_);
    rope_q<<<(M_*NH_)/8, 256, 0, s1>>>(pQh);
    cvt_h<<<(HID_*HID_)/2048, 256, 0, s1>>>(o_w, hOW);
    cudaEventRecord(eJoin, s1);

    // ---- main stream: KV chain ----
    cvt_h<<<(CKVW_*HID_)/2048, 256>>>(kv_a_w, hKAW);
    cvt_h<<<(NKV_*RANK_)/2048, 256>>>(kv_b_w, hKBW);
    gemm_h16<float><<<dim3((CKVW_+127)/128, M_/128), blk, GEMM_SMEM>>>(hHID, hKAW, pCKV, M_, CKVW_, HID_);
    rmsnorm_k<<<M_, 128>>>(pCKV, ln_w, pCLNh);
    gemm_h16<__half><<<dim3(NKV_/128, M_/128), blk, GEMM_SMEM>>>(pCLNh, hKBW, pKVh, M_, NKV_, RANK_);
    rope_k<<<M_/8, 256>>>(pCKV, pKPEh);

    // ---- join, then attention (per-batch) with O-proj(b0) overlapped ----
    cudaStreamWaitEvent(0, eJoin, 0);
    attn_fa2<<<dim3(S_/64, NH_, 1), 128, ATTN_SMEM>>>(pQh, pKVh, pKPEh, pAOh, 0);
    cudaEventRecord(eA0, 0);
    attn_fa2<<<dim3(S_/64, NH_, 1), 128, ATTN_SMEM>>>(pQh, pKVh, pKPEh, pAOh, 1);

    // s1: O-projection for batch-0 rows, overlapping attn(b=1)
    cudaStreamWaitEvent(s1, eA0, 0);
    gemm_h16<float><<<dim3(HID_/128, (M_/2)/128), blk, GEMM_SMEM, s1>>>(pAOh, hOW, out, M_/2, HID_, HID_);
    cudaEventRecord(eO0, s1);

    // main: O-projection for batch-1 rows, then join s1
    gemm_h16<float><<<dim3(HID_/128, (M_/2)/128), blk, GEMM_SMEM>>>(
        pAOh + (size_t)(M_/2) * HID_, hOW, out + (size_t)(M_/2) * HID_, M_/2, HID_, HID_);
    cudaStreamWaitEvent(0, eO0, 0);

    cudaEventDestroy(eFork);
    cudaEventDestroy(eJoin);
    cudaEventDestroy(eA0);
    cudaEventDestroy(eO0);
    cudaStreamDestroy(s1);
}

// round 15
// speedup vs baseline: 1.0536x; 1.0536x over previous
#include <cuda_runtime.h>
#include <cuda_fp16.h>
#include <math.h>
#include <stdint.h>

// Problem constants
#define B_     2
#define S_     2048
#define HID_   2048
#define NH_    16
#define DQ_    192
#define DNOPE_ 128
#define DROPE_ 64
#define DV_    128
#define RANK_  512
#define M_     (B_*S_)            // 4096
#define NQ_    (NH_*DQ_)          // 3072
#define NKV_   (NH_*(DNOPE_+DV_)) // 4096
#define CKVW_  (RANK_+DROPE_)     // 576

// Scratch (device globals; no runtime allocation allowed)
__device__ __half g_HIDh[M_*HID_];    // fp16 hidden
__device__ __half g_QWh [NQ_*HID_];   // fp16 weights
__device__ __half g_KAWh[CKVW_*HID_];
__device__ __half g_KBWh[NKV_*RANK_];
__device__ __half g_OWh [HID_*HID_];
__device__ __half g_Qh  [M_*NQ_];     // fp16 q projection (rope in place)
__device__ float  g_CKV [M_*CKVW_];   // kv_a output fp32 (c | k_pe raw)
__device__ __half g_CLNh[M_*RANK_];   // rmsnormed c (fp16)
__device__ __half g_KVh [M_*NKV_];    // fp16 kv_b output (k_nope | v)
__device__ __half g_KPEh[M_*DROPE_];  // fp16 rotated k_pe
__device__ __half g_AOh [M_*NH_*DV_]; // fp16 attention output

// ---------------------------------------------------------------------------
// Helpers
// ---------------------------------------------------------------------------
__device__ __forceinline__ uint32_t smem_u32(const void* p) {
    uint32_t a;
    asm("{ .reg .u64 t; cvta.to.shared.u64 t, %1; cvt.u32.u64 %0, t; }" : "=r"(a) : "l"(p));
    return a;
}
__device__ __forceinline__ unsigned h2u(float a, float b) {
    __half2 h = __floats2half2_rn(a, b);
    return *(unsigned*)&h;
}
// fp16 mma m16n8k16, fp32 accumulate
#define MMA16(C, A, B0, B1) \
    asm volatile("mma.sync.aligned.m16n8k16.row.col.f32.f16.f16.f32 " \
        "{%0,%1,%2,%3},{%4,%5,%6,%7},{%8,%9},{%0,%1,%2,%3};" \
        : "+f"((C)[0]), "+f"((C)[1]), "+f"((C)[2]), "+f"((C)[3]) \
        : "r"((A)[0]), "r"((A)[1]), "r"((A)[2]), "r"((A)[3]), "r"(B0), "r"(B1))

#define LDSM4(R, addr) \
    asm volatile("ldmatrix.sync.aligned.m8n8.x4.shared.b16 {%0,%1,%2,%3}, [%4];" \
        : "=r"((R)[0]), "=r"((R)[1]), "=r"((R)[2]), "=r"((R)[3]) : "r"(addr))
#define LDSM4T(R, addr) \
    asm volatile("ldmatrix.sync.aligned.m8n8.x4.trans.shared.b16 {%0,%1,%2,%3}, [%4];" \
        : "=r"((R)[0]), "=r"((R)[1]), "=r"((R)[2]), "=r"((R)[3]) : "r"(addr))

#define CPA16(dst, src) \
    asm volatile("cp.async.cg.shared.global [%0], [%1], 16;" :: "r"(dst), "l"(src))
#define CPA_COMMIT() asm volatile("cp.async.commit_group;" ::: "memory")
#define CPA_WAIT0()  asm volatile("cp.async.wait_group 0;" ::: "memory")

// Swizzled smem offset: rs-byte rows (rs multiple of 128), 16B chunk c
__device__ __forceinline__ uint32_t offN(uint32_t row, uint32_t rs, uint32_t c) {
    return row * rs + ((c >> 3) << 7) + (((c ^ row) & 7u) << 4);
}

// output store: fp32 or fp16 pair
__device__ __forceinline__ void store2(float* p, float a, float b) {
    *(float2*)p = make_float2(a, b);
}
__device__ __forceinline__ void store2(__half* p, float a, float b) {
    *(__half2*)p = __floats2half2_rn(a, b);
}

// ---------------------------------------------------------------------------
// fp32 -> fp16 bulk convert (8 elts/thread)
// ---------------------------------------------------------------------------
__global__ void cvt_h(const float* __restrict__ s, __half* __restrict__ d) {
    int i = (blockIdx.x * 256 + threadIdx.x) * 8;
    float4 a = *(const float4*)(s + i);
    float4 b = *(const float4*)(s + i + 4);
    uint4 pk;
    pk.x = h2u(a.x, a.y); pk.y = h2u(a.z, a.w);
    pk.z = h2u(b.x, b.y); pk.w = h2u(b.z, b.w);
    *(uint4*)(d + i) = pk;
}

// ---------------------------------------------------------------------------
// fp16 NT GEMM via cp.async: C[M][N] = A[M][K] * W[N][K]^T (A,W fp16)
// Tile 128x128x64, 256 threads, warps 4x2, double-buffered, 1 barrier/slab.
// DYNAMIC smem: 2 stages x (A 16K | B 16K) = 64K.  (unchanged from R10)
// ---------------------------------------------------------------------------
#define GEMM_SMEM (2 * 32768)

template <typename OutT>
__global__ __launch_bounds__(256, 2)
void gemm_h16(const __half* __restrict__ A, const __half* __restrict__ W,
              OutT* __restrict__ C, int M, int N, int K) {
    extern __shared__ __align__(16) uint8_t smraw[];
    uint32_t sb = smem_u32(smraw);
    int tid = threadIdx.x, lane = tid & 31, warp = tid >> 5;
    int wm = warp >> 1, wn = warp & 1;
    int m0 = blockIdx.y * 128, n0 = blockIdx.x * 128;

    int rJ[4], cJ[4], rnJ[4];
    #pragma unroll
    for (int i = 0; i < 4; i++) {
        int idx = tid + i * 256;
        rJ[i] = idx >> 3; cJ[i] = idx & 7;
        int rn = n0 + rJ[i]; rnJ[i] = (rn > N - 1) ? (N - 1) : rn;
    }

    auto stage = [&](int s, int st) {
        uint32_t ab = sb + st * 32768, bb = ab + 16384;
        int kof = s * 64;
        #pragma unroll
        for (int i = 0; i < 4; i++) {
            CPA16(ab + offN(rJ[i], 128, cJ[i]),
                  A + (size_t)(m0 + rJ[i]) * K + kof + cJ[i] * 8);
            CPA16(bb + offN(rJ[i], 128, cJ[i]),
                  W + (size_t)rnJ[i] * K + kof + cJ[i] * 8);
        }
        CPA_COMMIT();
    };

    float acc[2][8][4];
    #pragma unroll
    for (int a = 0; a < 2; a++)
        #pragma unroll
        for (int b = 0; b < 8; b++)
            #pragma unroll
            for (int c = 0; c < 4; c++) acc[a][b][c] = 0.0f;

    stage(0, 0);
    int ns = K >> 6;
    for (int s = 0; s < ns; s++) {
        int st = s & 1;
        CPA_WAIT0();           // slab s arrived
        __syncthreads();       // visible to all; prev compute done (buf reuse)
        if (s + 1 < ns) stage(s + 1, st ^ 1);   // prefetch (async)
        uint32_t ab = sb + st * 32768, bb = ab + 16384;
        #pragma unroll
        for (int ks = 0; ks < 4; ks++) {
            unsigned af[2][4];
            #pragma unroll
            for (int mt = 0; mt < 2; mt++) {
                uint32_t row = wm * 32 + mt * 16 + (lane & 15);
                uint32_t c = ks * 2 + (lane >> 4);
                LDSM4(af[mt], ab + offN(row, 128, c));
            }
            #pragma unroll
            for (int nb = 0; nb < 4; nb++) {
                unsigned bf[4];
                uint32_t rowb = wn * 64 + nb * 16 + (lane & 7) + ((lane >> 4) << 3);
                uint32_t cb = ks * 2 + ((lane >> 3) & 1);
                LDSM4(bf, bb + offN(rowb, 128, cb));
                MMA16(acc[0][nb*2],   af[0], bf[0], bf[1]);
                MMA16(acc[0][nb*2+1], af[0], bf[2], bf[3]);
                MMA16(acc[1][nb*2],   af[1], bf[0], bf[1]);
                MMA16(acc[1][nb*2+1], af[1], bf[2], bf[3]);
            }
        }
    }

    #pragma unroll
    for (int mt = 0; mt < 2; mt++) {
        int r0 = m0 + wm * 32 + mt * 16 + (lane >> 2);
        #pragma unroll
        for (int nt = 0; nt < 8; nt++) {
            int cb = n0 + wn * 64 + nt * 8 + (lane & 3) * 2;
            if (cb < N) {
                store2(&C[(size_t)r0 * N + cb],       acc[mt][nt][0], acc[mt][nt][1]);
                store2(&C[(size_t)(r0 + 8) * N + cb], acc[mt][nt][2], acc[mt][nt][3]);
            }
        }
    }
}

// ---------------------------------------------------------------------------
// RMSNorm over first 512 of each 576-wide CKV row, times gamma -> fp16.
// ---------------------------------------------------------------------------
__global__ void rmsnorm_k(const float* __restrict__ ckv, const float* __restrict__ w,
                          __half* __restrict__ out) {
    int m = blockIdx.x;
    int tid = threadIdx.x;   // 128 threads
    const float* row = ckv + (size_t)m * CKVW_;
    float4 v = *(const float4*)(row + tid * 4);
    float ss = v.x*v.x + v.y*v.y + v.z*v.z + v.w*v.w;
    #pragma unroll
    for (int o = 16; o; o >>= 1) ss += __shfl_xor_sync(0xffffffffu, ss, o);
    __shared__ float sacc[4];
    if ((tid & 31) == 0) sacc[tid >> 5] = ss;
    __syncthreads();
    float tot = sacc[0] + sacc[1] + sacc[2] + sacc[3];
    float inv = rsqrtf(tot * (1.0f/512.0f) + 1e-6f);
    float4 wv = *(const float4*)(w + tid * 4);
    uint2 pk;
    pk.x = h2u(v.x*inv*wv.x, v.y*inv*wv.y);
    pk.y = h2u(v.z*inv*wv.z, v.w*inv*wv.w);
    *(uint2*)(out + (size_t)m * RANK_ + tid * 4) = pk;
}

// ---------------------------------------------------------------------------
// YaRN rope (low=10, high=23, mscale ratio = 1). Position = m % S_.
// ---------------------------------------------------------------------------
__device__ __forceinline__ float yarn_inv_freq(int j) {
    float fe = powf(10000.0f, -(float)(2*j) / 64.0f);
    float fi = fe * (1.0f / 40.0f);
    float ramp = fminf(fmaxf(((float)j - 10.0f) * (1.0f/13.0f), 0.0f), 1.0f);
    return fi * ramp + fe * (1.0f - ramp);
}

__global__ void rope_q(__half* __restrict__ Q) {
    int warp = (blockIdx.x * blockDim.x + threadIdx.x) >> 5;
    int lane = threadIdx.x & 31;
    int m = warp >> 4, h = warp & 15;
    __half* p = Q + (size_t)m * NQ_ + h * DQ_ + DNOPE_;
    float x0 = __half2float(p[2*lane]), x1 = __half2float(p[2*lane+1]);
    float ang = (float)(m % S_) * yarn_inv_freq(lane);
    float s, c;
    sincosf(ang, &s, &c);
    float y0 = x0*c - x1*s;
    float y1 = x1*c + x0*s;
    __syncwarp();
    p[lane]      = __float2half(y0);
    p[lane + 32] = __float2half(y1);
}

__global__ void rope_k(const float* __restrict__ ckv, __half* __restrict__ kpe) {
    int warp = (blockIdx.x * blockDim.x + threadIdx.x) >> 5;
    int lane = threadIdx.x & 31;
    const float* p = ckv + (size_t)warp * CKVW_ + RANK_;
    float x0 = p[2*lane], x1 = p[2*lane+1];
    float ang = (float)(warp % S_) * yarn_inv_freq(lane);
    float s, c;
    sincosf(ang, &s, &c);
    kpe[(size_t)warp * DROPE_ + lane]      = __float2half(x0*c - x1*s);
    kpe[(size_t)warp * DROPE_ + lane + 32] = __float2half(x1*c + x0*s);
}

// ---------------------------------------------------------------------------
// Flash attention FA2-style, fp16 mma, cp.async double-buffered K/V.
// Block = (b, h, 64-q tile), 128 threads / 4 warps (R13/R10 topology: one
// launch over both batches). Each warp owns a 16-row q stripe x full 64-key
// tile: warp-local softmax, in-register P, ONE __syncthreads per k-tile.
// ONLY change vs R13: Q fragments loaded to REGISTERS once at kt==0; the 12
// Q-LDSM4s vanish from every later k-tile. (128,2): 255-reg budget, ~180
// used -> no spills, occupancy unchanged.
// Smem: Qs [64][192]h @0 (24K) | buf st @ 24576+st*40960: K 24K | V 16K.
// Total 106496 B -> 2 CTAs/SM.
// ---------------------------------------------------------------------------
#define AQ_OFF 0
#define BUF_OFF(st) (24576 + (st)*40960)
#define ATTN_SMEM 106496

__global__ __launch_bounds__(128, 2)
void attn_fa2(const __half* __restrict__ Qh, const __half* __restrict__ KVh,
              const __half* __restrict__ KPEh, __half* __restrict__ AOh) {
    extern __shared__ __align__(16) uint8_t smraw[];
    uint32_t sb = smem_u32(smraw);

    int tid = threadIdx.x, lane = tid & 31, warp = tid >> 5;
    int qt = gridDim.x - 1 - blockIdx.x;   // reverse: heavy tiles first
    int h = blockIdx.y, b = blockIdx.z;
    int q0 = qt * 64;
    const size_t base = (size_t)b * S_;

    auto stage_tile = [&](int kt, int st) {
        int k0 = kt * 64;
        uint32_t kb = sb + BUF_OFF(st), vb = kb + 24576;
        #pragma unroll
        for (int i = 0; i < 12; i++) {   // K: 64 rows x 24 chunks
            int idx = tid + i * 128;
            int r = idx / 24, c = idx % 24;
            const __half* src = (c < 16)
                ? KVh  + (base + k0 + r) * NKV_ + h * 256 + c * 8
                : KPEh + (base + k0 + r) * (size_t)DROPE_ + (c - 16) * 8;
            CPA16(kb + offN(r, 384, c), src);
        }
        #pragma unroll
        for (int i = 0; i < 8; i++) {    // V: 64 rows x 16 chunks
            int idx = tid + i * 128;
            int r = idx / 16, c = idx % 16;
            const __half* src = KVh + (base + k0 + r) * NKV_ + h * 256 + 128 + c * 8;
            CPA16(vb + offN(r, 256, c), src);
        }
        CPA_COMMIT();
    };

    // stage Q (once) + tile 0 as one group
    #pragma unroll
    for (int i = 0; i < 12; i++) {
        int idx = tid + i * 128;
        int r = idx / 24, c = idx % 24;
        const __half* src = Qh + (base + q0 + r) * NQ_ + h * DQ_ + c * 8;
        CPA16(sb + AQ_OFF + offN(r, 384, c), src);
    }
    stage_tile(0, 0);

    int wq = warp * 16;
    int grow0 = q0 + wq + (lane >> 2);   // global q rows of this thread
    int grow1 = grow0 + 8;

    float m_r[2] = {-INFINITY, -INFINITY};
    float l_r[2] = {0.0f, 0.0f};
    float o[16][4];
    #pragma unroll
    for (int nt = 0; nt < 16; nt++)
        #pragma unroll
        for (int j = 0; j < 4; j++) o[nt][j] = 0.0f;

    unsigned qf[12][4];                  // Q fragments (regs, loaded at kt==0)

    const float scale = 0.072168783648703f;   // 1/sqrt(192)

    for (int kt = 0; kt <= qt; kt++) {
        int k0 = kt * 64;
        int st = kt & 1;
        uint32_t kbuf = sb + BUF_OFF(st), vbuf = kbuf + 24576;
        CPA_WAIT0();           // tile kt (and Q) arrived
        __syncthreads();       // visibility + prior compute done (buf reuse)
        if (kt < qt) stage_tile(kt + 1, st ^ 1);   // async prefetch
        if (kt == 0) {
            #pragma unroll
            for (int ks = 0; ks < 12; ks++) {
                uint32_t row = wq + (lane & 15);
                uint32_t c = ks * 2 + (lane >> 4);
                LDSM4(qf[ks], sb + AQ_OFF + offN(row, 384, c));
            }
        }

        // S = Q K^T : warp m16 x n64, 12 k16 steps (Q from registers)
        float sacc[8][4];
        #pragma unroll
        for (int nt = 0; nt < 8; nt++)
            #pragma unroll
            for (int j = 0; j < 4; j++) sacc[nt][j] = 0.0f;
        #pragma unroll
        for (int ks = 0; ks < 12; ks++) {
            #pragma unroll
            for (int nb = 0; nb < 4; nb++) {
                unsigned kb[4];
                uint32_t rowb = nb * 16 + (lane & 7) + ((lane >> 4) << 3);
                uint32_t cb = ks * 2 + ((lane >> 3) & 1);
                LDSM4(kb, kbuf + offN(rowb, 384, cb));
                MMA16(sacc[nb*2],   qf[ks], kb[0], kb[1]);
                MMA16(sacc[nb*2+1], qf[ks], kb[2], kb[3]);
            }
        }
        // scale + causal mask (only tiles straddling the diagonal)
        bool diag = (k0 + 63 > q0 + wq);
        #pragma unroll
        for (int nt = 0; nt < 8; nt++) {
            int cb = k0 + nt * 8 + (lane & 3) * 2;
            #pragma unroll
            for (int j = 0; j < 4; j++) {
                float v = sacc[nt][j] * scale;
                if (diag) {
                    int col = cb + (j & 1);
                    int row = (j < 2) ? grow0 : grow1;
                    if (col > row) v = -1e30f;
                }
                sacc[nt][j] = v;
            }
        }
        // warp-local online softmax
        float mx0 = -INFINITY, mx1 = -INFINITY;
        #pragma unroll
        for (int nt = 0; nt < 8; nt++) {
            mx0 = fmaxf(mx0, fmaxf(sacc[nt][0], sacc[nt][1]));
            mx1 = fmaxf(mx1, fmaxf(sacc[nt][2], sacc[nt][3]));
        }
        mx0 = fmaxf(mx0, __shfl_xor_sync(0xffffffffu, mx0, 1));
        mx0 = fmaxf(mx0, __shfl_xor_sync(0xffffffffu, mx0, 2));
        mx1 = fmaxf(mx1, __shfl_xor_sync(0xffffffffu, mx1, 1));
        mx1 = fmaxf(mx1, __shfl_xor_sync(0xffffffffu, mx1, 2));
        float nm0 = fmaxf(m_r[0], mx0), nm1 = fmaxf(m_r[1], mx1);
        float corr0 = __expf(m_r[0] - nm0), corr1 = __expf(m_r[1] - nm1);
        m_r[0] = nm0; m_r[1] = nm1;

        float rs0 = 0.0f, rs1 = 0.0f;
        #pragma unroll
        for (int nt = 0; nt < 8; nt++) {
            sacc[nt][0] = __expf(sacc[nt][0] - nm0);
            sacc[nt][1] = __expf(sacc[nt][1] - nm0);
            sacc[nt][2] = __expf(sacc[nt][2] - nm1);
            sacc[nt][3] = __expf(sacc[nt][3] - nm1);
            rs0 += sacc[nt][0] + sacc[nt][1];
            rs1 += sacc[nt][2] + sacc[nt][3];
        }
        rs0 += __shfl_xor_sync(0xffffffffu, rs0, 1);
        rs0 += __shfl_xor_sync(0xffffffffu, rs0, 2);
        rs1 += __shfl_xor_sync(0xffffffffu, rs1, 1);
        rs1 += __shfl_xor_sync(0xffffffffu, rs1, 2);
        l_r[0] = l_r[0] * corr0 + rs0;
        l_r[1] = l_r[1] * corr1 + rs1;

        // O = O*corr + P V. P: in-register C-frag -> A-frag conversion.
        #pragma unroll
        for (int nt = 0; nt < 16; nt++) {
            o[nt][0] *= corr0; o[nt][1] *= corr0;
            o[nt][2] *= corr1; o[nt][3] *= corr1;
        }
        #pragma unroll
        for (int ks = 0; ks < 4; ks++) {
            unsigned pa[4];
            pa[0] = h2u(sacc[ks*2][0],   sacc[ks*2][1]);
            pa[1] = h2u(sacc[ks*2][2],   sacc[ks*2][3]);
            pa[2] = h2u(sacc[ks*2+1][0], sacc[ks*2+1][1]);
            pa[3] = h2u(sacc[ks*2+1][2], sacc[ks*2+1][3]);
            #pragma unroll
            for (int nb = 0; nb < 8; nb++) {
                unsigned vb[4];
                uint32_t row = ks * 16 + (lane & 7) + (((lane >> 3) & 1) << 3);
                uint32_t c = nb * 2 + (lane >> 4);
                LDSM4T(vb, vbuf + offN(row, 256, c));
                MMA16(o[nb*2],   pa, vb[0], vb[1]);
                MMA16(o[nb*2+1], pa, vb[2], vb[3]);
            }
        }
    }

    // epilogue: normalize, write fp16 AO[b,q,h*128+d]
    float inv0 = 1.0f / l_r[0], inv1 = 1.0f / l_r[1];
    #pragma unroll
    for (int nt = 0; nt < 16; nt++) {
        int d = nt * 8 + (lane & 3) * 2;
        size_t r0 = (base + grow0) * (size_t)(NH_*DV_) + h*DV_ + d;
        size_t r1 = (base + grow1) * (size_t)(NH_*DV_) + h*DV_ + d;
        store2(&AOh[r0], o[nt][0]*inv0, o[nt][1]*inv0);
        store2(&AOh[r1], o[nt][2]*inv1, o[nt][3]*inv1);
    }
}

// ---------------------------------------------------------------------------
// Launch: R13 topology exactly — fork-join front-end (Q branch || KV chain),
// single attention launch, single O-projection.
// ---------------------------------------------------------------------------
extern "C" void kernel_launch(void* const* d_in, const int* in_sizes, int n_in,
                              void* d_out, int out_size) {
    const float* hidden = (const float*)d_in[0];
    const float* q_w    = (const float*)d_in[2];
    const float* kv_a_w = (const float*)d_in[3];
    const float* ln_w   = (const float*)d_in[4];
    const float* kv_b_w = (const float*)d_in[5];
    const float* o_w    = (const float*)d_in[6];
    float*       out    = (float*)d_out;

    __half *hHID, *hQW, *hKAW, *hKBW, *hOW, *pQh, *pKVh, *pKPEh, *pCLNh, *pAOh;
    float  *pCKV;
    cudaGetSymbolAddress((void**)&hHID,  g_HIDh);
    cudaGetSymbolAddress((void**)&hQW,   g_QWh);
    cudaGetSymbolAddress((void**)&hKAW,  g_KAWh);
    cudaGetSymbolAddress((void**)&hKBW,  g_KBWh);
    cudaGetSymbolAddress((void**)&hOW,   g_OWh);
    cudaGetSymbolAddress((void**)&pQh,   g_Qh);
    cudaGetSymbolAddress((void**)&pCKV,  g_CKV);
    cudaGetSymbolAddress((void**)&pCLNh, g_CLNh);
    cudaGetSymbolAddress((void**)&pKVh,  g_KVh);
    cudaGetSymbolAddress((void**)&pKPEh, g_KPEh);
    cudaGetSymbolAddress((void**)&pAOh,  g_AOh);

    cudaFuncSetAttribute(attn_fa2, cudaFuncAttributeMaxDynamicSharedMemorySize,
                         (int)ATTN_SMEM);
    cudaFuncSetAttribute(gemm_h16<__half>, cudaFuncAttributeMaxDynamicSharedMemorySize,
                         (int)GEMM_SMEM);
    cudaFuncSetAttribute(gemm_h16<float>, cudaFuncAttributeMaxDynamicSharedMemorySize,
                         (int)GEMM_SMEM);

    cudaStream_t s1;
    cudaStreamCreateWithFlags(&s1, cudaStreamNonBlocking);
    cudaEvent_t eFork, eJoin;
    cudaEventCreateWithFlags(&eFork, cudaEventDisableTiming);
    cudaEventCreateWithFlags(&eJoin, cudaEventDisableTiming);

    dim3 blk(256);
    // ---- main stream: hidden cvt (shared dependency) ----
    cvt_h<<<(M_*HID_)/2048, 256>>>(hidden, hHID);
    cudaEventRecord(eFork, 0);

    // ---- branch s1: Q projection chain (+ o_w cvt) ----
    cudaStreamWaitEvent(s1, eFork, 0);
    cvt_h<<<(NQ_*HID_)/2048, 256, 0, s1>>>(q_w, hQW);
    gemm_h16<__half><<<dim3(NQ_/128, M_/128), blk, GEMM_SMEM, s1>>>(hHID, hQW, pQh, M_, NQ_, HID_);
    rope_q<<<(M_*NH_)/8, 256, 0, s1>>>(pQh);
    cvt_h<<<(HID_*HID_)/2048, 256, 0, s1>>>(o_w, hOW);
    cudaEventRecord(eJoin, s1);

    // ---- main stream: KV chain ----
    cvt_h<<<(CKVW_*HID_)/2048, 256>>>(kv_a_w, hKAW);
    cvt_h<<<(NKV_*RANK_)/2048, 256>>>(kv_b_w, hKBW);
    gemm_h16<float><<<dim3((CKVW_+127)/128, M_/128), blk, GEMM_SMEM>>>(hHID, hKAW, pCKV, M_, CKVW_, HID_);
    rmsnorm_k<<<M_, 128>>>(pCKV, ln_w, pCLNh);
    gemm_h16<__half><<<dim3(NKV_/128, M_/128), blk, GEMM_SMEM>>>(pCLNh, hKBW, pKVh, M_, NKV_, RANK_);
    rope_k<<<M_/8, 256>>>(pCKV, pKPEh);

    // ---- join, then attention + output projection (single launches) ----
    cudaStreamWaitEvent(0, eJoin, 0);
    attn_fa2<<<dim3(S_/64, NH_, B_), 128, ATTN_SMEM>>>(pQh, pKVh, pKPEh, pAOh);
    gemm_h16<float><<<dim3(HID_/128, M_/128), blk, GEMM_SMEM>>>(pAOh, hOW, out, M_, HID_, HID_);

    cudaEventDestroy(eFork);
    cudaEventDestroy(eJoin);
    cudaStreamDestroy(s1);
}

// round 16
// speedup vs baseline: 1.1456x; 1.0873x over previous
#include <cuda_runtime.h>
#include <cuda_fp16.h>
#include <math.h>
#include <stdint.h>

// Problem constants
#define B_     2
#define S_     2048
#define HID_   2048
#define NH_    16
#define DQ_    192
#define DNOPE_ 128
#define DROPE_ 64
#define DV_    128
#define RANK_  512
#define M_     (B_*S_)            // 4096
#define NQ_    (NH_*DQ_)          // 3072
#define NKV_   (NH_*(DNOPE_+DV_)) // 4096
#define CKVW_  (RANK_+DROPE_)     // 576

// Scratch (device globals; no runtime allocation allowed)
__device__ __half g_HIDh[M_*HID_];    // fp16 hidden
__device__ __half g_QWh [NQ_*HID_];   // fp16 weights
__device__ __half g_KAWh[CKVW_*HID_];
__device__ __half g_KBWh[NKV_*RANK_];
__device__ __half g_OWh [HID_*HID_];
__device__ __half g_Qh  [M_*NQ_];     // fp16 q projection (rope in place)
__device__ float  g_CKV [M_*CKVW_];   // kv_a output fp32 (c | k_pe raw)
__device__ __half g_CLNh[M_*RANK_];   // rmsnormed c (fp16)
__device__ __half g_KVh [M_*NKV_];    // fp16 kv_b output (k_nope | v)
__device__ __half g_KPEh[M_*DROPE_];  // fp16 rotated k_pe
__device__ __half g_AOh [M_*NH_*DV_]; // fp16 attention output

// ---------------------------------------------------------------------------
// Helpers
// ---------------------------------------------------------------------------
__device__ __forceinline__ uint32_t smem_u32(const void* p) {
    uint32_t a;
    asm("{ .reg .u64 t; cvta.to.shared.u64 t, %1; cvt.u32.u64 %0, t; }" : "=r"(a) : "l"(p));
    return a;
}
__device__ __forceinline__ unsigned h2u(float a, float b) {
    __half2 h = __floats2half2_rn(a, b);
    return *(unsigned*)&h;
}
// fp16 mma m16n8k16, fp32 accumulate
#define MMA16(C, A, B0, B1) \
    asm volatile("mma.sync.aligned.m16n8k16.row.col.f32.f16.f16.f32 " \
        "{%0,%1,%2,%3},{%4,%5,%6,%7},{%8,%9},{%0,%1,%2,%3};" \
        : "+f"((C)[0]), "+f"((C)[1]), "+f"((C)[2]), "+f"((C)[3]) \
        : "r"((A)[0]), "r"((A)[1]), "r"((A)[2]), "r"((A)[3]), "r"(B0), "r"(B1))

#define LDSM4(R, addr) \
    asm volatile("ldmatrix.sync.aligned.m8n8.x4.shared.b16 {%0,%1,%2,%3}, [%4];" \
        : "=r"((R)[0]), "=r"((R)[1]), "=r"((R)[2]), "=r"((R)[3]) : "r"(addr))
#define LDSM4T(R, addr) \
    asm volatile("ldmatrix.sync.aligned.m8n8.x4.trans.shared.b16 {%0,%1,%2,%3}, [%4];" \
        : "=r"((R)[0]), "=r"((R)[1]), "=r"((R)[2]), "=r"((R)[3]) : "r"(addr))

#define CPA16(dst, src) \
    asm volatile("cp.async.cg.shared.global [%0], [%1], 16;" :: "r"(dst), "l"(src))
#define CPA_COMMIT() asm volatile("cp.async.commit_group;" ::: "memory")
#define CPA_WAIT0()  asm volatile("cp.async.wait_group 0;" ::: "memory")

// Swizzled smem offset: rs-byte rows (rs multiple of 128), 16B chunk c
__device__ __forceinline__ uint32_t offN(uint32_t row, uint32_t rs, uint32_t c) {
    return row * rs + ((c >> 3) << 7) + (((c ^ row) & 7u) << 4);
}

// output store: fp32 or fp16 pair
__device__ __forceinline__ void store2(float* p, float a, float b) {
    *(float2*)p = make_float2(a, b);
}
__device__ __forceinline__ void store2(__half* p, float a, float b) {
    *(__half2*)p = __floats2half2_rn(a, b);
}

// ---------------------------------------------------------------------------
// fp32 -> fp16 bulk convert (8 elts/thread)
// ---------------------------------------------------------------------------
__global__ void cvt_h(const float* __restrict__ s, __half* __restrict__ d) {
    int i = (blockIdx.x * 256 + threadIdx.x) * 8;
    float4 a = *(const float4*)(s + i);
    float4 b = *(const float4*)(s + i + 4);
    uint4 pk;
    pk.x = h2u(a.x, a.y); pk.y = h2u(a.z, a.w);
    pk.z = h2u(b.x, b.y); pk.w = h2u(b.z, b.w);
    *(uint4*)(d + i) = pk;
}

// ---------------------------------------------------------------------------
// fp16 NT GEMM via cp.async: C[M][N] = A[M][K] * W[N][K]^T (A,W fp16)
// Tile 128x128x64, 256 threads, warps 4x2, double-buffered, 1 barrier/slab.
// DYNAMIC smem: 2 stages x (A 16K | B 16K) = 64K.
// ---------------------------------------------------------------------------
#define GEMM_SMEM (2 * 32768)

template <typename OutT>
__global__ __launch_bounds__(256, 2)
void gemm_h16(const __half* __restrict__ A, const __half* __restrict__ W,
              OutT* __restrict__ C, int M, int N, int K) {
    extern __shared__ __align__(16) uint8_t smraw[];
    uint32_t sb = smem_u32(smraw);
    int tid = threadIdx.x, lane = tid & 31, warp = tid >> 5;
    int wm = warp >> 1, wn = warp & 1;
    int m0 = blockIdx.y * 128, n0 = blockIdx.x * 128;

    int rJ[4], cJ[4], rnJ[4];
    #pragma unroll
    for (int i = 0; i < 4; i++) {
        int idx = tid + i * 256;
        rJ[i] = idx >> 3; cJ[i] = idx & 7;
        int rn = n0 + rJ[i]; rnJ[i] = (rn > N - 1) ? (N - 1) : rn;
    }

    auto stage = [&](int s, int st) {
        uint32_t ab = sb + st * 32768, bb = ab + 16384;
        int kof = s * 64;
        #pragma unroll
        for (int i = 0; i < 4; i++) {
            CPA16(ab + offN(rJ[i], 128, cJ[i]),
                  A + (size_t)(m0 + rJ[i]) * K + kof + cJ[i] * 8);
            CPA16(bb + offN(rJ[i], 128, cJ[i]),
                  W + (size_t)rnJ[i] * K + kof + cJ[i] * 8);
        }
        CPA_COMMIT();
    };

    float acc[2][8][4];
    #pragma unroll
    for (int a = 0; a < 2; a++)
        #pragma unroll
        for (int b = 0; b < 8; b++)
            #pragma unroll
            for (int c = 0; c < 4; c++) acc[a][b][c] = 0.0f;

    stage(0, 0);
    int ns = K >> 6;
    for (int s = 0; s < ns; s++) {
        int st = s & 1;
        CPA_WAIT0();           // slab s arrived
        __syncthreads();       // visible to all; prev compute done (buf reuse)
        if (s + 1 < ns) stage(s + 1, st ^ 1);   // prefetch (async)
        uint32_t ab = sb + st * 32768, bb = ab + 16384;
        #pragma unroll
        for (int ks = 0; ks < 4; ks++) {
            unsigned af[2][4];
            #pragma unroll
            for (int mt = 0; mt < 2; mt++) {
                uint32_t row = wm * 32 + mt * 16 + (lane & 15);
                uint32_t c = ks * 2 + (lane >> 4);
                LDSM4(af[mt], ab + offN(row, 128, c));
            }
            #pragma unroll
            for (int nb = 0; nb < 4; nb++) {
                unsigned bf[4];
                uint32_t rowb = wn * 64 + nb * 16 + (lane & 7) + ((lane >> 4) << 3);
                uint32_t cb = ks * 2 + ((lane >> 3) & 1);
                LDSM4(bf, bb + offN(rowb, 128, cb));
                MMA16(acc[0][nb*2],   af[0], bf[0], bf[1]);
                MMA16(acc[0][nb*2+1], af[0], bf[2], bf[3]);
                MMA16(acc[1][nb*2],   af[1], bf[0], bf[1]);
                MMA16(acc[1][nb*2+1], af[1], bf[2], bf[3]);
            }
        }
    }

    #pragma unroll
    for (int mt = 0; mt < 2; mt++) {
        int r0 = m0 + wm * 32 + mt * 16 + (lane >> 2);
        #pragma unroll
        for (int nt = 0; nt < 8; nt++) {
            int cb = n0 + wn * 64 + nt * 8 + (lane & 3) * 2;
            if (cb < N) {
                store2(&C[(size_t)r0 * N + cb],       acc[mt][nt][0], acc[mt][nt][1]);
                store2(&C[(size_t)(r0 + 8) * N + cb], acc[mt][nt][2], acc[mt][nt][3]);
            }
        }
    }
}

// ---------------------------------------------------------------------------
// RMSNorm over first 512 of each 576-wide CKV row, times gamma -> fp16.
// ---------------------------------------------------------------------------
__global__ void rmsnorm_k(const float* __restrict__ ckv, const float* __restrict__ w,
                          __half* __restrict__ out) {
    int m = blockIdx.x;
    int tid = threadIdx.x;   // 128 threads
    const float* row = ckv + (size_t)m * CKVW_;
    float4 v = *(const float4*)(row + tid * 4);
    float ss = v.x*v.x + v.y*v.y + v.z*v.z + v.w*v.w;
    #pragma unroll
    for (int o = 16; o; o >>= 1) ss += __shfl_xor_sync(0xffffffffu, ss, o);
    __shared__ float sacc[4];
    if ((tid & 31) == 0) sacc[tid >> 5] = ss;
    __syncthreads();
    float tot = sacc[0] + sacc[1] + sacc[2] + sacc[3];
    float inv = rsqrtf(tot * (1.0f/512.0f) + 1e-6f);
    float4 wv = *(const float4*)(w + tid * 4);
    uint2 pk;
    pk.x = h2u(v.x*inv*wv.x, v.y*inv*wv.y);
    pk.y = h2u(v.z*inv*wv.z, v.w*inv*wv.w);
    *(uint2*)(out + (size_t)m * RANK_ + tid * 4) = pk;
}

// ---------------------------------------------------------------------------
// YaRN rope (low=10, high=23, mscale ratio = 1). Position = m % S_.
// ---------------------------------------------------------------------------
__device__ __forceinline__ float yarn_inv_freq(int j) {
    float fe = powf(10000.0f, -(float)(2*j) / 64.0f);
    float fi = fe * (1.0f / 40.0f);
    float ramp = fminf(fmaxf(((float)j - 10.0f) * (1.0f/13.0f), 0.0f), 1.0f);
    return fi * ramp + fe * (1.0f - ramp);
}

__global__ void rope_q(__half* __restrict__ Q) {
    int warp = (blockIdx.x * blockDim.x + threadIdx.x) >> 5;
    int lane = threadIdx.x & 31;
    int m = warp >> 4, h = warp & 15;
    __half* p = Q + (size_t)m * NQ_ + h * DQ_ + DNOPE_;
    float x0 = __half2float(p[2*lane]), x1 = __half2float(p[2*lane+1]);
    float ang = (float)(m % S_) * yarn_inv_freq(lane);
    float s, c;
    sincosf(ang, &s, &c);
    float y0 = x0*c - x1*s;
    float y1 = x1*c + x0*s;
    __syncwarp();
    p[lane]      = __float2half(y0);
    p[lane + 32] = __float2half(y1);
}

__global__ void rope_k(const float* __restrict__ ckv, __half* __restrict__ kpe) {
    int warp = (blockIdx.x * blockDim.x + threadIdx.x) >> 5;
    int lane = threadIdx.x & 31;
    const float* p = ckv + (size_t)warp * CKVW_ + RANK_;
    float x0 = p[2*lane], x1 = p[2*lane+1];
    float ang = (float)(warp % S_) * yarn_inv_freq(lane);
    float s, c;
    sincosf(ang, &s, &c);
    kpe[(size_t)warp * DROPE_ + lane]      = __float2half(x0*c - x1*s);
    kpe[(size_t)warp * DROPE_ + lane + 32] = __float2half(x1*c + x0*s);
}

// ---------------------------------------------------------------------------
// Flash attention FA2-style, fp16 mma, cp.async double-buffered K/V.
// EXACT R13/R10 kernel (best measured): block = (b, h, 64-q tile), 128
// threads / 4 warps; warp-local softmax, in-register P, Q via per-tile LDSM,
// ONE __syncthreads per k-tile.
// Smem: Qs [64][192]h @0 (24K) | buf st @ 24576+st*40960: K 24K | V 16K.
// Total 106496 B -> 2 CTAs/SM.
// ---------------------------------------------------------------------------
#define AQ_OFF 0
#define BUF_OFF(st) (24576 + (st)*40960)
#define ATTN_SMEM 106496

__global__ __launch_bounds__(128, 2)
void attn_fa2(const __half* __restrict__ Qh, const __half* __restrict__ KVh,
              const __half* __restrict__ KPEh, __half* __restrict__ AOh) {
    extern __shared__ __align__(16) uint8_t smraw[];
    uint32_t sb = smem_u32(smraw);

    int tid = threadIdx.x, lane = tid & 31, warp = tid >> 5;
    int qt = gridDim.x - 1 - blockIdx.x;   // reverse: heavy tiles first
    int h = blockIdx.y, b = blockIdx.z;
    int q0 = qt * 64;
    const size_t base = (size_t)b * S_;

    auto stage_tile = [&](int kt, int st) {
        int k0 = kt * 64;
        uint32_t kb = sb + BUF_OFF(st), vb = kb + 24576;
        #pragma unroll
        for (int i = 0; i < 12; i++) {   // K: 64 rows x 24 chunks
            int idx = tid + i * 128;
            int r = idx / 24, c = idx % 24;
            const __half* src = (c < 16)
                ? KVh  + (base + k0 + r) * NKV_ + h * 256 + c * 8
                : KPEh + (base + k0 + r) * (size_t)DROPE_ + (c - 16) * 8;
            CPA16(kb + offN(r, 384, c), src);
        }
        #pragma unroll
        for (int i = 0; i < 8; i++) {    // V: 64 rows x 16 chunks
            int idx = tid + i * 128;
            int r = idx / 16, c = idx % 16;
            const __half* src = KVh + (base + k0 + r) * NKV_ + h * 256 + 128 + c * 8;
            CPA16(vb + offN(r, 256, c), src);
        }
        CPA_COMMIT();
    };

    // stage Q (once) + tile 0 as one group
    #pragma unroll
    for (int i = 0; i < 12; i++) {
        int idx = tid + i * 128;
        int r = idx / 24, c = idx % 24;
        const __half* src = Qh + (base + q0 + r) * NQ_ + h * DQ_ + c * 8;
        CPA16(sb + AQ_OFF + offN(r, 384, c), src);
    }
    stage_tile(0, 0);

    int wq = warp * 16;
    int grow0 = q0 + wq + (lane >> 2);   // global q rows of this thread
    int grow1 = grow0 + 8;

    float m_r[2] = {-INFINITY, -INFINITY};
    float l_r[2] = {0.0f, 0.0f};
    float o[16][4];
    #pragma unroll
    for (int nt = 0; nt < 16; nt++)
        #pragma unroll
        for (int j = 0; j < 4; j++) o[nt][j] = 0.0f;

    const float scale = 0.072168783648703f;   // 1/sqrt(192)

    for (int kt = 0; kt <= qt; kt++) {
        int k0 = kt * 64;
        int st = kt & 1;
        uint32_t kbuf = sb + BUF_OFF(st), vbuf = kbuf + 24576;
        CPA_WAIT0();           // tile kt (and Q) arrived
        __syncthreads();       // visibility + prior compute done (buf reuse)
        if (kt < qt) stage_tile(kt + 1, st ^ 1);   // async prefetch

        // S = Q K^T : warp m16 x n64, 12 k16 steps
        float sacc[8][4];
        #pragma unroll
        for (int nt = 0; nt < 8; nt++)
            #pragma unroll
            for (int j = 0; j < 4; j++) sacc[nt][j] = 0.0f;
        #pragma unroll
        for (int ks = 0; ks < 12; ks++) {
            unsigned qa[4];
            {
                uint32_t row = wq + (lane & 15);
                uint32_t c = ks * 2 + (lane >> 4);
                LDSM4(qa, sb + AQ_OFF + offN(row, 384, c));
            }
            #pragma unroll
            for (int nb = 0; nb < 4; nb++) {
                unsigned kb[4];
                uint32_t rowb = nb * 16 + (lane & 7) + ((lane >> 4) << 3);
                uint32_t cb = ks * 2 + ((lane >> 3) & 1);
                LDSM4(kb, kbuf + offN(rowb, 384, cb));
                MMA16(sacc[nb*2],   qa, kb[0], kb[1]);
                MMA16(sacc[nb*2+1], qa, kb[2], kb[3]);
            }
        }
        // scale + causal mask (only tiles straddling the diagonal)
        bool diag = (k0 + 63 > q0 + wq);
        #pragma unroll
        for (int nt = 0; nt < 8; nt++) {
            int cb = k0 + nt * 8 + (lane & 3) * 2;
            #pragma unroll
            for (int j = 0; j < 4; j++) {
                float v = sacc[nt][j] * scale;
                if (diag) {
                    int col = cb + (j & 1);
                    int row = (j < 2) ? grow0 : grow1;
                    if (col > row) v = -1e30f;
                }
                sacc[nt][j] = v;
            }
        }
        // warp-local online softmax
        float mx0 = -INFINITY, mx1 = -INFINITY;
        #pragma unroll
        for (int nt = 0; nt < 8; nt++) {
            mx0 = fmaxf(mx0, fmaxf(sacc[nt][0], sacc[nt][1]));
            mx1 = fmaxf(mx1, fmaxf(sacc[nt][2], sacc[nt][3]));
        }
        mx0 = fmaxf(mx0, __shfl_xor_sync(0xffffffffu, mx0, 1));
        mx0 = fmaxf(mx0, __shfl_xor_sync(0xffffffffu, mx0, 2));
        mx1 = fmaxf(mx1, __shfl_xor_sync(0xffffffffu, mx1, 1));
        mx1 = fmaxf(mx1, __shfl_xor_sync(0xffffffffu, mx1, 2));
        float nm0 = fmaxf(m_r[0], mx0), nm1 = fmaxf(m_r[1], mx1);
        float corr0 = __expf(m_r[0] - nm0), corr1 = __expf(m_r[1] - nm1);
        m_r[0] = nm0; m_r[1] = nm1;

        float rs0 = 0.0f, rs1 = 0.0f;
        #pragma unroll
        for (int nt = 0; nt < 8; nt++) {
            sacc[nt][0] = __expf(sacc[nt][0] - nm0);
            sacc[nt][1] = __expf(sacc[nt][1] - nm0);
            sacc[nt][2] = __expf(sacc[nt][2] - nm1);
            sacc[nt][3] = __expf(sacc[nt][3] - nm1);
            rs0 += sacc[nt][0] + sacc[nt][1];
            rs1 += sacc[nt][2] + sacc[nt][3];
        }
        rs0 += __shfl_xor_sync(0xffffffffu, rs0, 1);
        rs0 += __shfl_xor_sync(0xffffffffu, rs0, 2);
        rs1 += __shfl_xor_sync(0xffffffffu, rs1, 1);
        rs1 += __shfl_xor_sync(0xffffffffu, rs1, 2);
        l_r[0] = l_r[0] * corr0 + rs0;
        l_r[1] = l_r[1] * corr1 + rs1;

        // O = O*corr + P V. P: in-register C-frag -> A-frag conversion.
        #pragma unroll
        for (int nt = 0; nt < 16; nt++) {
            o[nt][0] *= corr0; o[nt][1] *= corr0;
            o[nt][2] *= corr1; o[nt][3] *= corr1;
        }
        #pragma unroll
        for (int ks = 0; ks < 4; ks++) {
            unsigned pa[4];
            pa[0] = h2u(sacc[ks*2][0],   sacc[ks*2][1]);
            pa[1] = h2u(sacc[ks*2][2],   sacc[ks*2][3]);
            pa[2] = h2u(sacc[ks*2+1][0], sacc[ks*2+1][1]);
            pa[3] = h2u(sacc[ks*2+1][2], sacc[ks*2+1][3]);
            #pragma unroll
            for (int nb = 0; nb < 8; nb++) {
                unsigned vb[4];
                uint32_t row = ks * 16 + (lane & 7) + (((lane >> 3) & 1) << 3);
                uint32_t c = nb * 2 + (lane >> 4);
                LDSM4T(vb, vbuf + offN(row, 256, c));
                MMA16(o[nb*2],   pa, vb[0], vb[1]);
                MMA16(o[nb*2+1], pa, vb[2], vb[3]);
            }
        }
    }

    // epilogue: normalize, write fp16 AO[b,q,h*128+d]
    float inv0 = 1.0f / l_r[0], inv1 = 1.0f / l_r[1];
    #pragma unroll
    for (int nt = 0; nt < 16; nt++) {
        int d = nt * 8 + (lane & 3) * 2;
        size_t r0 = (base + grow0) * (size_t)(NH_*DV_) + h*DV_ + d;
        size_t r1 = (base + grow1) * (size_t)(NH_*DV_) + h*DV_ + d;
        store2(&AOh[r0], o[nt][0]*inv0, o[nt][1]*inv0);
        store2(&AOh[r1], o[nt][2]*inv1, o[nt][3]*inv1);
    }
}

// ---------------------------------------------------------------------------
// Launch: R13 topology with a tightened critical path — the q_w / o_w weight
// conversions have no dependency on the hidden conversion, so s1 starts them
// immediately (rooted at eStart for capture legality) and only waits for
// hidden (eFork) before the Q projection.
// ---------------------------------------------------------------------------
extern "C" void kernel_launch(void* const* d_in, const int* in_sizes, int n_in,
                              void* d_out, int out_size) {
    const float* hidden = (const float*)d_in[0];
    const float* q_w    = (const float*)d_in[2];
    const float* kv_a_w = (const float*)d_in[3];
    const float* ln_w   = (const float*)d_in[4];
    const float* kv_b_w = (const float*)d_in[5];
    const float* o_w    = (const float*)d_in[6];
    float*       out    = (float*)d_out;

    __half *hHID, *hQW, *hKAW, *hKBW, *hOW, *pQh, *pKVh, *pKPEh, *pCLNh, *pAOh;
    float  *pCKV;
    cudaGetSymbolAddress((void**)&hHID,  g_HIDh);
    cudaGetSymbolAddress((void**)&hQW,   g_QWh);
    cudaGetSymbolAddress((void**)&hKAW,  g_KAWh);
    cudaGetSymbolAddress((void**)&hKBW,  g_KBWh);
    cudaGetSymbolAddress((void**)&hOW,   g_OWh);
    cudaGetSymbolAddress((void**)&pQh,   g_Qh);
    cudaGetSymbolAddress((void**)&pCKV,  g_CKV);
    cudaGetSymbolAddress((void**)&pCLNh, g_CLNh);
    cudaGetSymbolAddress((void**)&pKVh,  g_KVh);
    cudaGetSymbolAddress((void**)&pKPEh, g_KPEh);
    cudaGetSymbolAddress((void**)&pAOh,  g_AOh);

    cudaFuncSetAttribute(attn_fa2, cudaFuncAttributeMaxDynamicSharedMemorySize,
                         (int)ATTN_SMEM);
    cudaFuncSetAttribute(gemm_h16<__half>, cudaFuncAttributeMaxDynamicSharedMemorySize,
                         (int)GEMM_SMEM);
    cudaFuncSetAttribute(gemm_h16<float>, cudaFuncAttributeMaxDynamicSharedMemorySize,
                         (int)GEMM_SMEM);

    cudaStream_t s1;
    cudaStreamCreateWithFlags(&s1, cudaStreamNonBlocking);
    cudaEvent_t eStart, eFork, eJoin;
    cudaEventCreateWithFlags(&eStart, cudaEventDisableTiming);
    cudaEventCreateWithFlags(&eFork,  cudaEventDisableTiming);
    cudaEventCreateWithFlags(&eJoin,  cudaEventDisableTiming);

    dim3 blk(256);
    // ---- main stream: root event, then hidden cvt ----
    cudaEventRecord(eStart, 0);
    cvt_h<<<(M_*HID_)/2048, 256>>>(hidden, hHID);
    cudaEventRecord(eFork, 0);

    // ---- branch s1: weight cvts immediately (independent of hidden),
    //      then Q projection after hidden is ready ----
    cudaStreamWaitEvent(s1, eStart, 0);
    cvt_h<<<(NQ_*HID_)/2048, 256, 0, s1>>>(q_w, hQW);
    cvt_h<<<(HID_*HID_)/2048, 256, 0, s1>>>(o_w, hOW);
    cudaStreamWaitEvent(s1, eFork, 0);
    gemm_h16<__half><<<dim3(NQ_/128, M_/128), blk, GEMM_SMEM, s1>>>(hHID, hQW, pQh, M_, NQ_, HID_);
    rope_q<<<(M_*NH_)/8, 256, 0, s1>>>(pQh);
    cudaEventRecord(eJoin, s1);

    // ---- main stream: KV chain ----
    cvt_h<<<(CKVW_*HID_)/2048, 256>>>(kv_a_w, hKAW);
    cvt_h<<<(NKV_*RANK_)/2048, 256>>>(kv_b_w, hKBW);
    gemm_h16<float><<<dim3((CKVW_+127)/128, M_/128), blk, GEMM_SMEM>>>(hHID, hKAW, pCKV, M_, CKVW_, HID_);
    rmsnorm_k<<<M_, 128>>>(pCKV, ln_w, pCLNh);
    gemm_h16<__half><<<dim3(NKV_/128, M_/128), blk, GEMM_SMEM>>>(pCLNh, hKBW, pKVh, M_, NKV_, RANK_);
    rope_k<<<M_/8, 256>>>(pCKV, pKPEh);

    // ---- join, then attention + output projection (single launches) ----
    cudaStreamWaitEvent(0, eJoin, 0);
    attn_fa2<<<dim3(S_/64, NH_, B_), 128, ATTN_SMEM>>>(pQh, pKVh, pKPEh, pAOh);
    gemm_h16<float><<<dim3(HID_/128, M_/128), blk, GEMM_SMEM>>>(pAOh, hOW, out, M_, HID_, HID_);

    cudaEventDestroy(eStart);
    cudaEventDestroy(eFork);
    cudaEventDestroy(eJoin);
    cudaStreamDestroy(s1);
}

// round 17
// speedup vs baseline: 1.1624x; 1.0147x over previous
#include <cuda_runtime.h>
#include <cuda_fp16.h>
#include <math.h>
#include <stdint.h>

// Problem constants
#define B_     2
#define S_     2048
#define HID_   2048
#define NH_    16
#define DQ_    192
#define DNOPE_ 128
#define DROPE_ 64
#define DV_    128
#define RANK_  512
#define M_     (B_*S_)            // 4096
#define NQ_    (NH_*DQ_)          // 3072
#define NKV_   (NH_*(DNOPE_+DV_)) // 4096
#define CKVW_  (RANK_+DROPE_)     // 576

// scale(1/sqrt(192)) * log2(e): Q is pre-scaled so softmax runs in base-2
#define QSCALE (0.07216878364870323f * 1.44269504088896340f)

// Scratch (device globals; no runtime allocation allowed)
__device__ __half g_HIDh[M_*HID_];
__device__ __half g_QWh [NQ_*HID_];
__device__ __half g_KAWh[CKVW_*HID_];
__device__ __half g_KBWh[NKV_*RANK_];
__device__ __half g_OWh [HID_*HID_];
__device__ __half g_Qh  [M_*NQ_];     // fp16 q projection (rope+scale fused)
__device__ float  g_CKV [M_*CKVW_];   // kv_a output fp32 (c | k_pe raw)
__device__ __half g_CLNh[M_*RANK_];   // rmsnormed c (fp16)
__device__ __half g_KVh [M_*NKV_];    // fp16 kv_b output (k_nope | v)
__device__ __half g_KPEh[M_*DROPE_];  // fp16 rotated k_pe
__device__ __half g_AOh [M_*NH_*DV_]; // fp16 attention output

// ---------------------------------------------------------------------------
// Helpers
// ---------------------------------------------------------------------------
__device__ __forceinline__ uint32_t smem_u32(const void* p) {
    uint32_t a;
    asm("{ .reg .u64 t; cvta.to.shared.u64 t, %1; cvt.u32.u64 %0, t; }" : "=r"(a) : "l"(p));
    return a;
}
__device__ __forceinline__ unsigned h2u(float a, float b) {
    __half2 h = __floats2half2_rn(a, b);
    return *(unsigned*)&h;
}
__device__ __forceinline__ float ex2f(float x) {
    float r; asm("ex2.approx.f32 %0, %1;" : "=f"(r) : "f"(x)); return r;
}
// fp16 mma m16n8k16, fp32 accumulate
#define MMA16(C, A, B0, B1) \
    asm volatile("mma.sync.aligned.m16n8k16.row.col.f32.f16.f16.f32 " \
        "{%0,%1,%2,%3},{%4,%5,%6,%7},{%8,%9},{%0,%1,%2,%3};" \
        : "+f"((C)[0]), "+f"((C)[1]), "+f"((C)[2]), "+f"((C)[3]) \
        : "r"((A)[0]), "r"((A)[1]), "r"((A)[2]), "r"((A)[3]), "r"(B0), "r"(B1))

#define LDSM4(R, addr) \
    asm volatile("ldmatrix.sync.aligned.m8n8.x4.shared.b16 {%0,%1,%2,%3}, [%4];" \
        : "=r"((R)[0]), "=r"((R)[1]), "=r"((R)[2]), "=r"((R)[3]) : "r"(addr))
#define LDSM4T(R, addr) \
    asm volatile("ldmatrix.sync.aligned.m8n8.x4.trans.shared.b16 {%0,%1,%2,%3}, [%4];" \
        : "=r"((R)[0]), "=r"((R)[1]), "=r"((R)[2]), "=r"((R)[3]) : "r"(addr))

#define CPA16(dst, src) \
    asm volatile("cp.async.cg.shared.global [%0], [%1], 16;" :: "r"(dst), "l"(src))
#define CPA_COMMIT() asm volatile("cp.async.commit_group;" ::: "memory")
#define CPA_WAIT0()  asm volatile("cp.async.wait_group 0;" ::: "memory")

// Swizzled smem offset: rs-byte rows (rs multiple of 128), 16B chunk c
__device__ __forceinline__ uint32_t offN(uint32_t row, uint32_t rs, uint32_t c) {
    return row * rs + ((c >> 3) << 7) + (((c ^ row) & 7u) << 4);
}

// output store: fp32 or fp16 pair
__device__ __forceinline__ void store2(float* p, float a, float b) {
    *(float2*)p = make_float2(a, b);
}
__device__ __forceinline__ void store2(__half* p, float a, float b) {
    *(__half2*)p = __floats2half2_rn(a, b);
}

// ---------------------------------------------------------------------------
// YaRN rope inv freq (low=10, high=23, mscale ratio = 1)
// ---------------------------------------------------------------------------
__device__ __forceinline__ float yarn_inv_freq(int j) {
    float fe = powf(10000.0f, -(float)(2*j) / 64.0f);
    float fi = fe * (1.0f / 40.0f);
    float ramp = fminf(fmaxf(((float)j - 10.0f) * (1.0f/13.0f), 0.0f), 1.0f);
    return fi * ramp + fe * (1.0f - ramp);
}

// ---------------------------------------------------------------------------
// fp32 -> fp16 bulk convert (8 elts/thread)
// ---------------------------------------------------------------------------
__global__ void cvt_h(const float* __restrict__ s, __half* __restrict__ d) {
    int i = (blockIdx.x * 256 + threadIdx.x) * 8;
    float4 a = *(const float4*)(s + i);
    float4 b = *(const float4*)(s + i + 4);
    uint4 pk;
    pk.x = h2u(a.x, a.y); pk.y = h2u(a.z, a.w);
    pk.z = h2u(b.x, b.y); pk.w = h2u(b.z, b.w);
    *(uint4*)(d + i) = pk;
}

// ---------------------------------------------------------------------------
// fp16 NT GEMM via cp.async: C[M][N] = A[M][K] * W[N][K]^T (A,W fp16)
// Tile 128x128x64, 256 threads, warps 4x2, double-buffered, 1 barrier/slab.
// ---------------------------------------------------------------------------
#define GEMM_SMEM (2 * 32768)

template <typename OutT>
__global__ __launch_bounds__(256, 2)
void gemm_h16(const __half* __restrict__ A, const __half* __restrict__ W,
              OutT* __restrict__ C, int M, int N, int K) {
    extern __shared__ __align__(16) uint8_t smraw[];
    uint32_t sb = smem_u32(smraw);
    int tid = threadIdx.x, lane = tid & 31, warp = tid >> 5;
    int wm = warp >> 1, wn = warp & 1;
    int m0 = blockIdx.y * 128, n0 = blockIdx.x * 128;

    int rJ[4], cJ[4], rnJ[4];
    #pragma unroll
    for (int i = 0; i < 4; i++) {
        int idx = tid + i * 256;
        rJ[i] = idx >> 3; cJ[i] = idx & 7;
        int rn = n0 + rJ[i]; rnJ[i] = (rn > N - 1) ? (N - 1) : rn;
    }

    auto stage = [&](int s, int st) {
        uint32_t ab = sb + st * 32768, bb = ab + 16384;
        int kof = s * 64;
        #pragma unroll
        for (int i = 0; i < 4; i++) {
            CPA16(ab + offN(rJ[i], 128, cJ[i]),
                  A + (size_t)(m0 + rJ[i]) * K + kof + cJ[i] * 8);
            CPA16(bb + offN(rJ[i], 128, cJ[i]),
                  W + (size_t)rnJ[i] * K + kof + cJ[i] * 8);
        }
        CPA_COMMIT();
    };

    float acc[2][8][4];
    #pragma unroll
    for (int a = 0; a < 2; a++)
        #pragma unroll
        for (int b = 0; b < 8; b++)
            #pragma unroll
            for (int c = 0; c < 4; c++) acc[a][b][c] = 0.0f;

    stage(0, 0);
    int ns = K >> 6;
    for (int s = 0; s < ns; s++) {
        int st = s & 1;
        CPA_WAIT0();
        __syncthreads();
        if (s + 1 < ns) stage(s + 1, st ^ 1);
        uint32_t ab = sb + st * 32768, bb = ab + 16384;
        #pragma unroll
        for (int ks = 0; ks < 4; ks++) {
            unsigned af[2][4];
            #pragma unroll
            for (int mt = 0; mt < 2; mt++) {
                uint32_t row = wm * 32 + mt * 16 + (lane & 15);
                uint32_t c = ks * 2 + (lane >> 4);
                LDSM4(af[mt], ab + offN(row, 128, c));
            }
            #pragma unroll
            for (int nb = 0; nb < 4; nb++) {
                unsigned bf[4];
                uint32_t rowb = wn * 64 + nb * 16 + (lane & 7) + ((lane >> 4) << 3);
                uint32_t cb = ks * 2 + ((lane >> 3) & 1);
                LDSM4(bf, bb + offN(rowb, 128, cb));
                MMA16(acc[0][nb*2],   af[0], bf[0], bf[1]);
                MMA16(acc[0][nb*2+1], af[0], bf[2], bf[3]);
                MMA16(acc[1][nb*2],   af[1], bf[0], bf[1]);
                MMA16(acc[1][nb*2+1], af[1], bf[2], bf[3]);
            }
        }
    }

    #pragma unroll
    for (int mt = 0; mt < 2; mt++) {
        int r0 = m0 + wm * 32 + mt * 16 + (lane >> 2);
        #pragma unroll
        for (int nt = 0; nt < 8; nt++) {
            int cb = n0 + wn * 64 + nt * 8 + (lane & 3) * 2;
            if (cb < N) {
                store2(&C[(size_t)r0 * N + cb],       acc[mt][nt][0], acc[mt][nt][1]);
                store2(&C[(size_t)(r0 + 8) * N + cb], acc[mt][nt][2], acc[mt][nt][3]);
            }
        }
    }
}

// ---------------------------------------------------------------------------
// Q-projection GEMM with FUSED rope + QSCALE epilogue. Same mainloop as
// gemm_h16; epilogue rotates the rope column-pairs in fp32 and pre-scales
// ALL columns by QSCALE (= 1/sqrt(192) * log2 e) so attention softmax runs
// in base-2 with no per-score multiply.
// ---------------------------------------------------------------------------
__global__ __launch_bounds__(256, 2)
void gemm_q16(const __half* __restrict__ A, const __half* __restrict__ W,
              __half* __restrict__ C, int M, int N, int K) {
    extern __shared__ __align__(16) uint8_t smraw[];
    uint32_t sb = smem_u32(smraw);
    int tid = threadIdx.x, lane = tid & 31, warp = tid >> 5;
    int wm = warp >> 1, wn = warp & 1;
    int m0 = blockIdx.y * 128, n0 = blockIdx.x * 128;

    int rJ[4], cJ[4], rnJ[4];
    #pragma unroll
    for (int i = 0; i < 4; i++) {
        int idx = tid + i * 256;
        rJ[i] = idx >> 3; cJ[i] = idx & 7;
        int rn = n0 + rJ[i]; rnJ[i] = (rn > N - 1) ? (N - 1) : rn;
    }

    auto stage = [&](int s, int st) {
        uint32_t ab = sb + st * 32768, bb = ab + 16384;
        int kof = s * 64;
        #pragma unroll
        for (int i = 0; i < 4; i++) {
            CPA16(ab + offN(rJ[i], 128, cJ[i]),
                  A + (size_t)(m0 + rJ[i]) * K + kof + cJ[i] * 8);
            CPA16(bb + offN(rJ[i], 128, cJ[i]),
                  W + (size_t)rnJ[i] * K + kof + cJ[i] * 8);
        }
        CPA_COMMIT();
    };

    float acc[2][8][4];
    #pragma unroll
    for (int a = 0; a < 2; a++)
        #pragma unroll
        for (int b = 0; b < 8; b++)
            #pragma unroll
            for (int c = 0; c < 4; c++) acc[a][b][c] = 0.0f;

    stage(0, 0);
    int ns = K >> 6;
    for (int s = 0; s < ns; s++) {
        int st = s & 1;
        CPA_WAIT0();
        __syncthreads();
        if (s + 1 < ns) stage(s + 1, st ^ 1);
        uint32_t ab = sb + st * 32768, bb = ab + 16384;
        #pragma unroll
        for (int ks = 0; ks < 4; ks++) {
            unsigned af[2][4];
            #pragma unroll
            for (int mt = 0; mt < 2; mt++) {
                uint32_t row = wm * 32 + mt * 16 + (lane & 15);
                uint32_t c = ks * 2 + (lane >> 4);
                LDSM4(af[mt], ab + offN(row, 128, c));
            }
            #pragma unroll
            for (int nb = 0; nb < 4; nb++) {
                unsigned bf[4];
                uint32_t rowb = wn * 64 + nb * 16 + (lane & 7) + ((lane >> 4) << 3);
                uint32_t cb = ks * 2 + ((lane >> 3) & 1);
                LDSM4(bf, bb + offN(rowb, 128, cb));
                MMA16(acc[0][nb*2],   af[0], bf[0], bf[1]);
                MMA16(acc[0][nb*2+1], af[0], bf[2], bf[3]);
                MMA16(acc[1][nb*2],   af[1], bf[0], bf[1]);
                MMA16(acc[1][nb*2+1], af[1], bf[2], bf[3]);
            }
        }
    }

    // epilogue: rope on cols with (c % 192) >= 128, QSCALE everywhere
    #pragma unroll
    for (int mt = 0; mt < 2; mt++) {
        int r0 = m0 + wm * 32 + mt * 16 + (lane >> 2);
        int p0 = r0 & (S_ - 1);          // position (M = 2*S, power of 2)
        int p1 = (r0 + 8) & (S_ - 1);
        #pragma unroll
        for (int nt = 0; nt < 8; nt++) {
            int cb = n0 + wn * 64 + nt * 8 + (lane & 3) * 2;
            int hc = cb % 192;
            float a0 = acc[mt][nt][0], a1 = acc[mt][nt][1];
            float a2 = acc[mt][nt][2], a3 = acc[mt][nt][3];
            if (hc < 128) {
                store2(&C[(size_t)r0 * N + cb],       a0 * QSCALE, a1 * QSCALE);
                store2(&C[(size_t)(r0 + 8) * N + cb], a2 * QSCALE, a3 * QSCALE);
            } else {
                int j = (hc - 128) >> 1;
                float invf = yarn_inv_freq(j);
                int csel = cb - hc + 128 + j;     // target col for y0 (y1 at +32)
                float s0, c0, s1, c1;
                sincosf((float)p0 * invf, &s0, &c0);
                sincosf((float)p1 * invf, &s1, &c1);
                C[(size_t)r0 * N + csel]          = __float2half((a0*c0 - a1*s0) * QSCALE);
                C[(size_t)r0 * N + csel + 32]     = __float2half((a1*c0 + a0*s0) * QSCALE);
                C[(size_t)(r0+8) * N + csel]      = __float2half((a2*c1 - a3*s1) * QSCALE);
                C[(size_t)(r0+8) * N + csel + 32] = __float2half((a3*c1 + a2*s1) * QSCALE);
            }
        }
    }
}

// ---------------------------------------------------------------------------
// RMSNorm (512 cols) -> fp16, with FUSED rope_k on cols 512..575 (warp 0).
// ---------------------------------------------------------------------------
__global__ void rmsnorm_rope_k(const float* __restrict__ ckv, const float* __restrict__ w,
                               __half* __restrict__ out, __half* __restrict__ kpe) {
    int m = blockIdx.x;
    int tid = threadIdx.x;   // 128 threads
    const float* row = ckv + (size_t)m * CKVW_;
    float4 v = *(const float4*)(row + tid * 4);
    float ss = v.x*v.x + v.y*v.y + v.z*v.z + v.w*v.w;
    #pragma unroll
    for (int o = 16; o; o >>= 1) ss += __shfl_xor_sync(0xffffffffu, ss, o);
    __shared__ float sacc[4];
    if ((tid & 31) == 0) sacc[tid >> 5] = ss;
    __syncthreads();
    float tot = sacc[0] + sacc[1] + sacc[2] + sacc[3];
    float inv = rsqrtf(tot * (1.0f/512.0f) + 1e-6f);
    float4 wv = *(const float4*)(w + tid * 4);
    uint2 pk;
    pk.x = h2u(v.x*inv*wv.x, v.y*inv*wv.y);
    pk.y = h2u(v.z*inv*wv.z, v.w*inv*wv.w);
    *(uint2*)(out + (size_t)m * RANK_ + tid * 4) = pk;

    if (tid < 32) {   // fused rope_k (identical math to the old kernel)
        const float* pr = row + RANK_;
        float x0 = pr[2*tid], x1 = pr[2*tid+1];
        float ang = (float)(m % S_) * yarn_inv_freq(tid);
        float s, c;
        sincosf(ang, &s, &c);
        kpe[(size_t)m * DROPE_ + tid]      = __float2half(x0*c - x1*s);
        kpe[(size_t)m * DROPE_ + tid + 32] = __float2half(x1*c + x0*s);
    }
}

// ---------------------------------------------------------------------------
// Flash attention FA2-style (R13 pipeline). Scores arrive PRE-SCALED in the
// base-2 domain (QSCALE folded into Q), so softmax uses raw ex2 and no
// per-score multiply. Everything else identical to the best-measured kernel.
// Smem: Qs [64][192]h @0 (24K) | buf st @ 24576+st*40960: K 24K | V 16K.
// Total 106496 B -> 2 CTAs/SM.
// ---------------------------------------------------------------------------
#define AQ_OFF 0
#define BUF_OFF(st) (24576 + (st)*40960)
#define ATTN_SMEM 106496

__global__ __launch_bounds__(128, 2)
void attn_fa2(const __half* __restrict__ Qh, const __half* __restrict__ KVh,
              const __half* __restrict__ KPEh, __half* __restrict__ AOh) {
    extern __shared__ __align__(16) uint8_t smraw[];
    uint32_t sb = smem_u32(smraw);

    int tid = threadIdx.x, lane = tid & 31, warp = tid >> 5;
    int qt = gridDim.x - 1 - blockIdx.x;   // reverse: heavy tiles first
    int h = blockIdx.y, b = blockIdx.z;
    int q0 = qt * 64;
    const size_t base = (size_t)b * S_;

    auto stage_tile = [&](int kt, int st) {
        int k0 = kt * 64;
        uint32_t kb = sb + BUF_OFF(st), vb = kb + 24576;
        #pragma unroll
        for (int i = 0; i < 12; i++) {
            int idx = tid + i * 128;
            int r = idx / 24, c = idx % 24;
            const __half* src = (c < 16)
                ? KVh  + (base + k0 + r) * NKV_ + h * 256 + c * 8
                : KPEh + (base + k0 + r) * (size_t)DROPE_ + (c - 16) * 8;
            CPA16(kb + offN(r, 384, c), src);
        }
        #pragma unroll
        for (int i = 0; i < 8; i++) {
            int idx = tid + i * 128;
            int r = idx / 16, c = idx % 16;
            const __half* src = KVh + (base + k0 + r) * NKV_ + h * 256 + 128 + c * 8;
            CPA16(vb + offN(r, 256, c), src);
        }
        CPA_COMMIT();
    };

    #pragma unroll
    for (int i = 0; i < 12; i++) {
        int idx = tid + i * 128;
        int r = idx / 24, c = idx % 24;
        const __half* src = Qh + (base + q0 + r) * NQ_ + h * DQ_ + c * 8;
        CPA16(sb + AQ_OFF + offN(r, 384, c), src);
    }
    stage_tile(0, 0);

    int wq = warp * 16;
    int grow0 = q0 + wq + (lane >> 2);
    int grow1 = grow0 + 8;

    float m_r[2] = {-INFINITY, -INFINITY};
    float l_r[2] = {0.0f, 0.0f};
    float o[16][4];
    #pragma unroll
    for (int nt = 0; nt < 16; nt++)
        #pragma unroll
        for (int j = 0; j < 4; j++) o[nt][j] = 0.0f;

    for (int kt = 0; kt <= qt; kt++) {
        int k0 = kt * 64;
        int st = kt & 1;
        uint32_t kbuf = sb + BUF_OFF(st), vbuf = kbuf + 24576;
        CPA_WAIT0();
        __syncthreads();
        if (kt < qt) stage_tile(kt + 1, st ^ 1);

        // S = Q K^T (already scaled, base-2 domain)
        float sacc[8][4];
        #pragma unroll
        for (int nt = 0; nt < 8; nt++)
            #pragma unroll
            for (int j = 0; j < 4; j++) sacc[nt][j] = 0.0f;
        #pragma unroll
        for (int ks = 0; ks < 12; ks++) {
            unsigned qa[4];
            {
                uint32_t row = wq + (lane & 15);
                uint32_t c = ks * 2 + (lane >> 4);
                LDSM4(qa, sb + AQ_OFF + offN(row, 384, c));
            }
            #pragma unroll
            for (int nb = 0; nb < 4; nb++) {
                unsigned kb[4];
                uint32_t rowb = nb * 16 + (lane & 7) + ((lane >> 4) << 3);
                uint32_t cb = ks * 2 + ((lane >> 3) & 1);
                LDSM4(kb, kbuf + offN(rowb, 384, cb));
                MMA16(sacc[nb*2],   qa, kb[0], kb[1]);
                MMA16(sacc[nb*2+1], qa, kb[2], kb[3]);
            }
        }
        // causal mask (diagonal tiles only); no scale multiply needed
        bool diag = (k0 + 63 > q0 + wq);
        if (diag) {
            #pragma unroll
            for (int nt = 0; nt < 8; nt++) {
                int cb = k0 + nt * 8 + (lane & 3) * 2;
                #pragma unroll
                for (int j = 0; j < 4; j++) {
                    int col = cb + (j & 1);
                    int row = (j < 2) ? grow0 : grow1;
                    if (col > row) sacc[nt][j] = -1e30f;
                }
            }
        }
        // warp-local online softmax (base-2)
        float mx0 = -INFINITY, mx1 = -INFINITY;
        #pragma unroll
        for (int nt = 0; nt < 8; nt++) {
            mx0 = fmaxf(mx0, fmaxf(sacc[nt][0], sacc[nt][1]));
            mx1 = fmaxf(mx1, fmaxf(sacc[nt][2], sacc[nt][3]));
        }
        mx0 = fmaxf(mx0, __shfl_xor_sync(0xffffffffu, mx0, 1));
        mx0 = fmaxf(mx0, __shfl_xor_sync(0xffffffffu, mx0, 2));
        mx1 = fmaxf(mx1, __shfl_xor_sync(0xffffffffu, mx1, 1));
        mx1 = fmaxf(mx1, __shfl_xor_sync(0xffffffffu, mx1, 2));
        float nm0 = fmaxf(m_r[0], mx0), nm1 = fmaxf(m_r[1], mx1);
        float corr0 = ex2f(m_r[0] - nm0), corr1 = ex2f(m_r[1] - nm1);
        m_r[0] = nm0; m_r[1] = nm1;

        float rs0 = 0.0f, rs1 = 0.0f;
        #pragma unroll
        for (int nt = 0; nt < 8; nt++) {
            sacc[nt][0] = ex2f(sacc[nt][0] - nm0);
            sacc[nt][1] = ex2f(sacc[nt][1] - nm0);
            sacc[nt][2] = ex2f(sacc[nt][2] - nm1);
            sacc[nt][3] = ex2f(sacc[nt][3] - nm1);
            rs0 += sacc[nt][0] + sacc[nt][1];
            rs1 += sacc[nt][2] + sacc[nt][3];
        }
        rs0 += __shfl_xor_sync(0xffffffffu, rs0, 1);
        rs0 += __shfl_xor_sync(0xffffffffu, rs0, 2);
        rs1 += __shfl_xor_sync(0xffffffffu, rs1, 1);
        rs1 += __shfl_xor_sync(0xffffffffu, rs1, 2);
        l_r[0] = l_r[0] * corr0 + rs0;
        l_r[1] = l_r[1] * corr1 + rs1;

        #pragma unroll
        for (int nt = 0; nt < 16; nt++) {
            o[nt][0] *= corr0; o[nt][1] *= corr0;
            o[nt][2] *= corr1; o[nt][3] *= corr1;
        }
        #pragma unroll
        for (int ks = 0; ks < 4; ks++) {
            unsigned pa[4];
            pa[0] = h2u(sacc[ks*2][0],   sacc[ks*2][1]);
            pa[1] = h2u(sacc[ks*2][2],   sacc[ks*2][3]);
            pa[2] = h2u(sacc[ks*2+1][0], sacc[ks*2+1][1]);
            pa[3] = h2u(sacc[ks*2+1][2], sacc[ks*2+1][3]);
            #pragma unroll
            for (int nb = 0; nb < 8; nb++) {
                unsigned vb[4];
                uint32_t row = ks * 16 + (lane & 7) + (((lane >> 3) & 1) << 3);
                uint32_t c = nb * 2 + (lane >> 4);
                LDSM4T(vb, vbuf + offN(row, 256, c));
                MMA16(o[nb*2],   pa, vb[0], vb[1]);
                MMA16(o[nb*2+1], pa, vb[2], vb[3]);
            }
        }
    }

    float inv0 = 1.0f / l_r[0], inv1 = 1.0f / l_r[1];
    #pragma unroll
    for (int nt = 0; nt < 16; nt++) {
        int d = nt * 8 + (lane & 3) * 2;
        size_t r0 = (base + grow0) * (size_t)(NH_*DV_) + h*DV_ + d;
        size_t r1 = (base + grow1) * (size_t)(NH_*DV_) + h*DV_ + d;
        store2(&AOh[r0], o[nt][0]*inv0, o[nt][1]*inv0);
        store2(&AOh[r1], o[nt][2]*inv1, o[nt][3]*inv1);
    }
}

// ---------------------------------------------------------------------------
// Launch: 3-stream DAG.
//   main: hidden cvt -> KVA -> rmsnorm+rope_k -> KVB -> [join] attn -> O-proj
//   s1:   qw cvt -> (wait hidden) Q-proj(fused rope)       [Q-branch pole]
//   s2:   kva cvt, kvb cvt, ow cvt                         [feeds main]
// ---------------------------------------------------------------------------
extern "C" void kernel_launch(void* const* d_in, const int* in_sizes, int n_in,
                              void* d_out, int out_size) {
    const float* hidden = (const float*)d_in[0];
    const float* q_w    = (const float*)d_in[2];
    const float* kv_a_w = (const float*)d_in[3];
    const float* ln_w   = (const float*)d_in[4];
    const float* kv_b_w = (const float*)d_in[5];
    const float* o_w    = (const float*)d_in[6];
    float*       out    = (float*)d_out;

    __half *hHID, *hQW, *hKAW, *hKBW, *hOW, *pQh, *pKVh, *pKPEh, *pCLNh, *pAOh;
    float  *pCKV;
    cudaGetSymbolAddress((void**)&hHID,  g_HIDh);
    cudaGetSymbolAddress((void**)&hQW,   g_QWh);
    cudaGetSymbolAddress((void**)&hKAW,  g_KAWh);
    cudaGetSymbolAddress((void**)&hKBW,  g_KBWh);
    cudaGetSymbolAddress((void**)&hOW,   g_OWh);
    cudaGetSymbolAddress((void**)&pQh,   g_Qh);
    cudaGetSymbolAddress((void**)&pCKV,  g_CKV);
    cudaGetSymbolAddress((void**)&pCLNh, g_CLNh);
    cudaGetSymbolAddress((void**)&pKVh,  g_KVh);
    cudaGetSymbolAddress((void**)&pKPEh, g_KPEh);
    cudaGetSymbolAddress((void**)&pAOh,  g_AOh);

    cudaFuncSetAttribute(attn_fa2, cudaFuncAttributeMaxDynamicSharedMemorySize,
                         (int)ATTN_SMEM);
    cudaFuncSetAttribute(gemm_h16<__half>, cudaFuncAttributeMaxDynamicSharedMemorySize,
                         (int)GEMM_SMEM);
    cudaFuncSetAttribute(gemm_h16<float>, cudaFuncAttributeMaxDynamicSharedMemorySize,
                         (int)GEMM_SMEM);
    cudaFuncSetAttribute(gemm_q16, cudaFuncAttributeMaxDynamicSharedMemorySize,
                         (int)GEMM_SMEM);

    cudaStream_t s1, s2;
    cudaStreamCreateWithFlags(&s1, cudaStreamNonBlocking);
    cudaStreamCreateWithFlags(&s2, cudaStreamNonBlocking);
    cudaEvent_t eStart, eFork, eKva, eKvb, eOw, eJoin;
    cudaEventCreateWithFlags(&eStart, cudaEventDisableTiming);
    cudaEventCreateWithFlags(&eFork,  cudaEventDisableTiming);
    cudaEventCreateWithFlags(&eKva,   cudaEventDisableTiming);
    cudaEventCreateWithFlags(&eKvb,   cudaEventDisableTiming);
    cudaEventCreateWithFlags(&eOw,    cudaEventDisableTiming);
    cudaEventCreateWithFlags(&eJoin,  cudaEventDisableTiming);

    dim3 blk(256);
    // ---- main: hidden cvt ----
    cudaEventRecord(eStart, 0);
    cvt_h<<<(M_*HID_)/2048, 256>>>(hidden, hHID);
    cudaEventRecord(eFork, 0);

    // ---- s1: qw cvt, then Q-proj (fused rope+scale) after hidden ----
    cudaStreamWaitEvent(s1, eStart, 0);
    cvt_h<<<(NQ_*HID_)/2048, 256, 0, s1>>>(q_w, hQW);
    cudaStreamWaitEvent(s1, eFork, 0);
    gemm_q16<<<dim3(NQ_/128, M_/128), blk, GEMM_SMEM, s1>>>(hHID, hQW, pQh, M_, NQ_, HID_);
    cudaEventRecord(eJoin, s1);

    // ---- s2: kv-a, kv-b, o_w weight cvts ----
    cudaStreamWaitEvent(s2, eStart, 0);
    cvt_h<<<(CKVW_*HID_)/2048, 256, 0, s2>>>(kv_a_w, hKAW);
    cudaEventRecord(eKva, s2);
    cvt_h<<<(NKV_*RANK_)/2048, 256, 0, s2>>>(kv_b_w, hKBW);
    cudaEventRecord(eKvb, s2);
    cvt_h<<<(HID_*HID_)/2048, 256, 0, s2>>>(o_w, hOW);
    cudaEventRecord(eOw, s2);

    // ---- main: KV chain ----
    cudaStreamWaitEvent(0, eKva, 0);
    gemm_h16<float><<<dim3((CKVW_+127)/128, M_/128), blk, GEMM_SMEM>>>(hHID, hKAW, pCKV, M_, CKVW_, HID_);
    rmsnorm_rope_k<<<M_, 128>>>(pCKV, ln_w, pCLNh, pKPEh);
    cudaStreamWaitEvent(0, eKvb, 0);
    gemm_h16<__half><<<dim3(NKV_/128, M_/128), blk, GEMM_SMEM>>>(pCLNh, hKBW, pKVh, M_, NKV_, RANK_);

    // ---- join, attention, output projection ----
    cudaStreamWaitEvent(0, eJoin, 0);
    attn_fa2<<<dim3(S_/64, NH_, B_), 128, ATTN_SMEM>>>(pQh, pKVh, pKPEh, pAOh);
    cudaStreamWaitEvent(0, eOw, 0);
    gemm_h16<float><<<dim3(HID_/128, M_/128), blk, GEMM_SMEM>>>(pAOh, hOW, out, M_, HID_, HID_);

    cudaEventDestroy(eStart);
    cudaEventDestroy(eFork);
    cudaEventDestroy(eKva);
    cudaEventDestroy(eKvb);
    cudaEventDestroy(eOw);
    cudaEventDestroy(eJoin);
    cudaStreamDestroy(s1);
    cudaStreamDestroy(s2);
}